// round 2
// baseline (speedup 1.0000x reference)
#include <cuda_runtime.h>
#include <cuda_bf16.h>
#include <cstdint>

// Dims
#define T 64
#define B 8
#define H 128
#define NH 4
#define D 256
#define HB (NH*B)          // 32
#define TB (T*B)           // 512
#define EPS 1e-5f
#define INV_SQRT_D 0.0625f // 1/sqrt(256)

// ---------------- scratch (device globals; no allocation) ----------------
__device__ float g_xin [T*B*D];      // [t][b][d]
__device__ float g_trig[T*B*D];      // [t][b][d]  silu'd
__device__ float g_qk  [T*NH*B*D];   // [t][h][b][d]
__device__ float g_ipre[T*HB];       // i_t pre-act  [t][h*B+b]
__device__ float g_fpre[T*HB];       // f_t pre-act
__device__ float g_ad  [T*HB];       // a_s = i_s - CF_s
__device__ float g_bd  [T*HB];       // b_t = CF_t - m_t
__device__ float g_q [NH*B*T*D];     // [h][b][t][e]
__device__ float g_k [NH*B*T*D];
__device__ float g_v [NH*B*T*D];
__device__ float g_og[NH*B*T*D];
__device__ float g_sk[NH*B*T*D];
__device__ float g_h [T*NH*B*D];     // [t][h][b][d]

// ---------------- K1: per-t BN1 + up-projections + conv/qk + gate pre-acts ----
__global__ void k1_pre(const float* __restrict__ x,
                       const float* __restrict__ bn1_s, const float* __restrict__ bn1_b,
                       const float* __restrict__ Wup1,  const float* __restrict__ bup1,
                       const float* __restrict__ Wup2,  const float* __restrict__ bup2,
                       const float* __restrict__ convk, const float* __restrict__ convb,
                       const float* __restrict__ Wi,    const float* __restrict__ bi,
                       const float* __restrict__ Wf,    const float* __restrict__ bf)
{
    int t = blockIdx.x;
    int tid = threadIdx.x;  // 256
    __shared__ float xs[B*H];
    __shared__ float us[B*H];
    __shared__ float xins[B*D];

    for (int i = tid; i < B*H; i += 256) xs[i] = x[t*B*H + i];
    __syncthreads();

    // BN1: stats over batch per feature
    if (tid < H) {
        int j = tid;
        float s = 0.f, s2 = 0.f;
        #pragma unroll
        for (int bb = 0; bb < B; bb++) { float v = xs[bb*H + j]; s += v; s2 += v*v; }
        float mu  = s * (1.f/B);
        float var = s2 * (1.f/B) - mu*mu;
        float inv = rsqrtf(var + EPS);
        float sc = bn1_s[j]*inv, ofs = bn1_b[j];
        #pragma unroll
        for (int bb = 0; bb < B; bb++) us[bb*H + j] = (xs[bb*H + j] - mu)*sc + ofs;
    }
    __syncthreads();

    // xin = u@Wup1+b ; trig = silu(u@Wup2+b).  One output column e per thread.
    {
        int e = tid;
        float a1[B], a2[B];
        #pragma unroll
        for (int bb = 0; bb < B; bb++) { a1[bb] = 0.f; a2[bb] = 0.f; }
        for (int j = 0; j < H; j++) {
            float w1 = Wup1[j*D + e];
            float w2 = Wup2[j*D + e];
            #pragma unroll
            for (int bb = 0; bb < B; bb++) {
                float uv = us[bb*H + j];
                a1[bb] = fmaf(uv, w1, a1[bb]);
                a2[bb] = fmaf(uv, w2, a2[bb]);
            }
        }
        float b1v = bup1[e], b2v = bup2[e];
        #pragma unroll
        for (int bb = 0; bb < B; bb++) {
            float xv = a1[bb] + b1v;
            xins[bb*D + e] = xv;
            g_xin[(t*B + bb)*D + e] = xv;
            float tv = a2[bb] + b2v;
            g_trig[(t*B + bb)*D + e] = tv / (1.f + expf(-tv));
        }
    }
    __syncthreads();

    // conv (SAME, k=4, pad_left=1) over feature axis + silu -> qk
    for (int idx = tid; idx < NH*B*D; idx += 256) {
        int hh = idx / (B*D);
        int rem = idx % (B*D);
        int bb = rem / D, dd = rem % D;
        float acc = convb[hh];
        #pragma unroll
        for (int w = 0; w < 4; w++) {
            int dj = dd - 1 + w;
            if (dj >= 0 && dj < D) acc = fmaf(xins[bb*D + dj], convk[w*NH + hh], acc);
        }
        g_qk[((t*NH + hh)*B + bb)*D + dd] = acc / (1.f + expf(-acc));
    }

    // gate pre-activations: i = xin.Wi + bi ; f = xin.Wf + bf
    if (tid < 2*HB) {
        int which = tid / HB;
        int p = tid % HB;
        int hh = p / B, bb = p % B;
        const float* W = which ? Wf : Wi;
        float acc = which ? bf[hh] : bi[hh];
        for (int dd = 0; dd < D; dd++) acc = fmaf(xins[bb*D + dd], W[hh*D + dd], acc);
        if (which) g_fpre[t*HB + p] = acc; else g_ipre[t*HB + p] = acc;
    }
}

// ---------------- K2: tiny per-(h,b) scalar scan: m_t, cumsum f ---------------
__global__ void k2_scan()
{
    int p = threadIdx.x;
    if (p >= HB) return;
    float m = 0.f, cf = 0.f;
    for (int t = 0; t < T; t++) {
        float f = g_fpre[t*HB + p];
        float i = g_ipre[t*HB + p];
        cf += f;
        float mn = fmaxf(f + m, i);
        g_ad[t*HB + p] = i - cf;    // a_s
        g_bd[t*HB + p] = cf - mn;   // b_t
        m = mn;
    }
}

// ---------------- K3: batched projection GEMMs -------------------------------
// 20 instances (proj 0..4 x head 0..3): C[512,256] = A[512,256] @ W[h][256,256]
// proj: 0=q(A=qk) 1=k(A=qk) 2=v(A=xin) 3=outg(A=xin) 4=skip(A=qk)
__global__ __launch_bounds__(256) void k3_gemm(
    const float* __restrict__ Wq, const float* __restrict__ bq,
    const float* __restrict__ Wk, const float* __restrict__ bk,
    const float* __restrict__ Wv, const float* __restrict__ bv,
    const float* __restrict__ Wo, const float* __restrict__ bo,
    const float* __restrict__ Wsk,const float* __restrict__ bsk)
{
    int inst = blockIdx.y;           // 0..19
    int proj = inst / NH;
    int h    = inst % NH;
    int tile = blockIdx.x;           // 0..31
    int tm = tile & 7;               // M tile (64 rows)
    int tn = tile >> 3;              // N tile (64 cols)

    const float* W; const float* bias; int src;
    switch (proj) {
        case 0: W = Wq;  bias = bq;  src = 0; break;
        case 1: W = Wk;  bias = bk;  src = 0; break;
        case 2: W = Wv;  bias = bv;  src = 1; break;
        case 3: W = Wo;  bias = bo;  src = 1; break;
        default:W = Wsk; bias = bsk; src = 0; break;
    }

    __shared__ float As[64*17];
    __shared__ float Bs[16*65];

    int tid = threadIdx.x;
    int tx = tid & 15;        // col group
    int ty = tid >> 4;        // row group

    float acc[4][4];
    #pragma unroll
    for (int i = 0; i < 4; i++)
        #pragma unroll
        for (int j = 0; j < 4; j++) acc[i][j] = 0.f;

    const float* Wb = W + (size_t)h*D*D;

    for (int kt = 0; kt < D/16; kt++) {
        // load A tile 64x16
        #pragma unroll
        for (int i = 0; i < 4; i++) {
            int e = tid + 256*i;
            int r = e >> 4, c = e & 15;
            int gr = tm*64 + r;
            int t = gr >> 3, bb = gr & 7;
            int d = kt*16 + c;
            float av = (src == 0) ? g_qk[((t*NH + h)*B + bb)*D + d]
                                  : g_xin[(t*B + bb)*D + d];
            As[r*17 + c] = av;
        }
        // load B tile 16x64
        #pragma unroll
        for (int i = 0; i < 4; i++) {
            int e = tid + 256*i;
            int kr = e >> 6, cc = e & 63;
            Bs[kr*65 + cc] = Wb[(kt*16 + kr)*D + tn*64 + cc];
        }
        __syncthreads();
        #pragma unroll
        for (int kk = 0; kk < 16; kk++) {
            float ar[4], br[4];
            #pragma unroll
            for (int i = 0; i < 4; i++) ar[i] = As[(ty*4 + i)*17 + kk];
            #pragma unroll
            for (int j = 0; j < 4; j++) br[j] = Bs[kk*65 + tx + 16*j];
            #pragma unroll
            for (int i = 0; i < 4; i++)
                #pragma unroll
                for (int j = 0; j < 4; j++) acc[i][j] = fmaf(ar[i], br[j], acc[i][j]);
        }
        __syncthreads();
    }

    // epilogue
    #pragma unroll
    for (int i = 0; i < 4; i++) {
        int gr = tm*64 + ty*4 + i;
        int t = gr >> 3, bb = gr & 7;
        #pragma unroll
        for (int j = 0; j < 4; j++) {
            int e = tn*64 + tx + 16*j;
            float v = acc[i][j] + bias[h*D + e];
            size_t oidx = ((size_t)(h*B + bb)*T + t)*D + e;
            switch (proj) {
                case 0: g_q [oidx] = v; break;
                case 1: g_k [oidx] = v * INV_SQRT_D; break;
                case 2: g_v [oidx] = v; break;
                case 3: g_og[oidx] = 1.f / (1.f + expf(-v)); break;
                default:g_sk[oidx] = v; break;
            }
        }
    }
}

// ---------------- K4: masked decayed attention per (h,b) ---------------------
#define QS_OFF 0
#define KS_OFF (64*257)
#define WS_OFF (KS_OFF + 64*257)
#define AD_OFF (WS_OFF + 64*65)
#define BD_OFF (AD_OFF + 64)
#define SC_OFF (BD_OFF + 64)
#define SM4_FLOATS (SC_OFF + 64)

extern __shared__ float sm4[];

__global__ __launch_bounds__(256) void k4_attn()
{
    int hb = blockIdx.x;          // (h*B + b)
    int h = hb / B, b = hb % B;
    int tid = threadIdx.x;

    float* Qs = sm4 + QS_OFF;
    float* Ks = sm4 + KS_OFF;     // reused for V
    float* Ws = sm4 + WS_OFF;
    float* ad = sm4 + AD_OFF;
    float* bd = sm4 + BD_OFF;
    float* sc = sm4 + SC_OFF;

    const float* Qg = g_q + (size_t)hb*T*D;
    const float* Kg = g_k + (size_t)hb*T*D;

    for (int i = tid; i < T*D; i += 256) {
        int t = i / D, e = i % D;
        Qs[t*257 + e] = Qg[i];
        Ks[t*257 + e] = Kg[i];
    }
    for (int i = tid; i < T; i += 256) {
        ad[i] = g_ad[i*HB + hb];
        bd[i] = g_bd[i*HB + hb];
    }
    __syncthreads();

    // scores + decay weight + causal mask
    for (int idx = tid; idx < T*T; idx += 256) {
        int t = idx / T, s = idx % T;
        float w = 0.f;
        if (s <= t) {
            float dot = 0.f;
            #pragma unroll 8
            for (int e = 0; e < D; e++) dot = fmaf(Qs[t*257 + e], Ks[s*257 + e], dot);
            w = expf(ad[s] + bd[t]) * dot;
        }
        Ws[t*65 + s] = w;
    }
    __syncthreads();

    if (tid < T) {
        float r = 0.f;
        for (int s = 0; s < T; s++) r += Ws[tid*65 + s];
        sc[tid] = 1.f / fmaxf(fabsf(r), 1.f);   // == 1/max(|n.q|,1)
    }
    __syncthreads();

    // reload V into Ks space
    const float* Vg = g_v + (size_t)hb*T*D;
    for (int i = tid; i < T*D; i += 256) {
        int t = i / D, e = i % D;
        Ks[t*257 + e] = Vg[i];
    }
    __syncthreads();

    // O = W @ V ; fuse outg * scaler + skip ; write h
    const float* OGg = g_og + (size_t)hb*T*D;
    const float* SKg = g_sk + (size_t)hb*T*D;
    int e = tid;  // one column per thread
    for (int t = 0; t < T; t++) {
        float accv = 0.f;
        for (int s = 0; s <= t; s++) accv = fmaf(Ws[t*65 + s], Ks[s*257 + e], accv);
        float hv = OGg[t*D + e] * accv * sc[t] + SKg[t*D + e];
        g_h[((t*NH + h)*B + b)*D + e] = hv;
    }
}

// ---------------- K5: BN2 + poll + trig-gate + down + residual ----------------
__global__ __launch_bounds__(256) void k5_tail(
    const float* __restrict__ x,
    const float* __restrict__ bn2_s, const float* __restrict__ bn2_b,
    const float* __restrict__ Wpoll, const float* __restrict__ bpoll,
    const float* __restrict__ Wdown, const float* __restrict__ bdown,
    float* __restrict__ out)
{
    int t = blockIdx.x;
    int tid = threadIdx.x;
    __shared__ float hs[NH*B*D];   // 32KB
    __shared__ float ps[B*D];      // 8KB

    for (int i = tid; i < NH*B*D; i += 256) hs[i] = g_h[(size_t)t*NH*B*D + i];
    __syncthreads();

    // BN2: per-feature stats over (h,b) = 32 values
    if (tid < D) {
        int d = tid;
        float s = 0.f, s2 = 0.f;
        #pragma unroll
        for (int p = 0; p < HB; p++) { float v = hs[p*D + d]; s += v; s2 += v*v; }
        float mu = s * (1.f/HB);
        float var = s2 * (1.f/HB) - mu*mu;
        float inv = rsqrtf(var + EPS);
        float scv = bn2_s[d]*inv, ofs = bn2_b[d];
        #pragma unroll
        for (int p = 0; p < HB; p++) hs[p*D + d] = (hs[p*D + d] - mu)*scv + ofs;
    }
    __syncthreads();

    // poll: [b, nh*d] @ Wpoll + bpoll, then * trig
    {
        int e = tid;
        float acc[B];
        #pragma unroll
        for (int bb = 0; bb < B; bb++) acc[bb] = 0.f;
        for (int hd = 0; hd < NH*D; hd++) {
            float w = Wpoll[hd*D + e];
            int hh = hd >> 8, dd = hd & 255;
            #pragma unroll
            for (int bb = 0; bb < B; bb++)
                acc[bb] = fmaf(hs[(hh*B + bb)*D + dd], w, acc[bb]);
        }
        float bp = bpoll[e];
        #pragma unroll
        for (int bb = 0; bb < B; bb++)
            ps[bb*D + e] = (acc[bb] + bp) * g_trig[(t*B + bb)*D + e];
    }
    __syncthreads();

    // down + residual
    {
        int j = tid & 127;
        int bg = tid >> 7;   // 0/1, 4 batches each
        float acc[4] = {0.f, 0.f, 0.f, 0.f};
        for (int e = 0; e < D; e++) {
            float w = Wdown[e*H + j];
            #pragma unroll
            for (int q = 0; q < 4; q++) acc[q] = fmaf(ps[(bg*4 + q)*D + e], w, acc[q]);
        }
        #pragma unroll
        for (int q = 0; q < 4; q++) {
            int bb = bg*4 + q;
            out[(t*B + bb)*H + j] = acc[q] + bdown[j] + x[(t*B + bb)*H + j];
        }
    }
}

// ---------------- launch -----------------------------------------------------
extern "C" void kernel_launch(void* const* d_in, const int* in_sizes, int n_in,
                              void* d_out, int out_size)
{
    const float* x      = (const float*)d_in[0];
    const float* Wq     = (const float*)d_in[1];
    const float* bq     = (const float*)d_in[2];
    const float* Wk     = (const float*)d_in[3];
    const float* bk     = (const float*)d_in[4];
    const float* Wv     = (const float*)d_in[5];
    const float* bv     = (const float*)d_in[6];
    const float* convk  = (const float*)d_in[7];
    const float* convb  = (const float*)d_in[8];
    const float* Wi     = (const float*)d_in[9];
    const float* bi     = (const float*)d_in[10];
    const float* Wf     = (const float*)d_in[11];
    const float* bf     = (const float*)d_in[12];
    const float* Wo     = (const float*)d_in[13];
    const float* bo     = (const float*)d_in[14];
    const float* Wsk    = (const float*)d_in[15];
    const float* bsk    = (const float*)d_in[16];
    const float* bn1_s  = (const float*)d_in[17];
    const float* bn1_b  = (const float*)d_in[18];
    const float* bn2_s  = (const float*)d_in[19];
    const float* bn2_b  = (const float*)d_in[20];
    const float* Wup1   = (const float*)d_in[21];
    const float* bup1   = (const float*)d_in[22];
    const float* Wup2   = (const float*)d_in[23];
    const float* bup2   = (const float*)d_in[24];
    const float* Wpoll  = (const float*)d_in[25];
    const float* bpoll  = (const float*)d_in[26];
    const float* Wdown  = (const float*)d_in[27];
    const float* bdown  = (const float*)d_in[28];
    float* out = (float*)d_out;

    // K4 needs ~146KB dynamic smem
    static const size_t sm4_bytes = SM4_FLOATS * sizeof(float);
    cudaFuncSetAttribute(k4_attn, cudaFuncAttributeMaxDynamicSharedMemorySize,
                         (int)sm4_bytes);

    k1_pre<<<T, 256>>>(x, bn1_s, bn1_b, Wup1, bup1, Wup2, bup2,
                       convk, convb, Wi, bi, Wf, bf);
    k2_scan<<<1, 32>>>();
    k3_gemm<<<dim3(32, 20), 256>>>(Wq, bq, Wk, bk, Wv, bv, Wo, bo, Wsk, bsk);
    k4_attn<<<HB, 256, sm4_bytes>>>();
    k5_tail<<<T, 256>>>(x, bn2_s, bn2_b, Wpoll, bpoll, Wdown, bdown, out);
}

// round 4
// speedup vs baseline: 1.4514x; 1.4514x over previous
#include <cuda_runtime.h>
#include <cuda_bf16.h>
#include <cstdint>

// Dims
#define T 64
#define B 8
#define H 128
#define NH 4
#define D 256
#define HB (NH*B)          // 32
#define EPS 1e-5f
#define INV_SQRT_D 0.0625f

// ---------------- scratch (device globals; no allocation) ----------------
__device__ float g_xin [T*B*D];
__device__ float g_trig[T*B*D];
__device__ float g_qk  [T*NH*B*D];
__device__ float g_ipre[T*HB];
__device__ float g_fpre[T*HB];
__device__ float g_ad  [T*HB];
__device__ float g_bd  [T*HB];
__device__ float g_q [NH*B*T*D];     // [hb][t][e]
__device__ float g_k [NH*B*T*D];
__device__ float g_v [NH*B*T*D];
__device__ float g_og[NH*B*T*D];
__device__ float g_sk[NH*B*T*D];
__device__ float g_w [HB*T*T];       // decayed masked scores [hb][t][s]
__device__ float g_sc[HB*T];         // 1/max(|n.q|,1)
__device__ float g_h [T*NH*B*D];     // [t][h][b][d]
__device__ float g_hn[T*B*NH*D];     // BN2'd, [(t*B+b)][h*D+d]
__device__ float g_pp[2*T*B*D];      // poll partials [kz][(t*B+b)][e]

// ---------------- K1: BN1 + up-proj + conv/qk + gate pre-acts ----------------
__global__ void k1_pre(const float* __restrict__ x,
                       const float* __restrict__ bn1_s, const float* __restrict__ bn1_b,
                       const float* __restrict__ Wup1,  const float* __restrict__ bup1,
                       const float* __restrict__ Wup2,  const float* __restrict__ bup2,
                       const float* __restrict__ convk, const float* __restrict__ convb,
                       const float* __restrict__ Wi,    const float* __restrict__ bi,
                       const float* __restrict__ Wf,    const float* __restrict__ bf)
{
    int t = blockIdx.x;
    int tid = threadIdx.x;  // 256
    __shared__ float xs[B*H];
    __shared__ float us[B*H];
    __shared__ float xins[B*D];

    for (int i = tid; i < B*H; i += 256) xs[i] = x[t*B*H + i];
    __syncthreads();

    if (tid < H) {
        int j = tid;
        float s = 0.f, s2 = 0.f;
        #pragma unroll
        for (int bb = 0; bb < B; bb++) { float v = xs[bb*H + j]; s += v; s2 += v*v; }
        float mu  = s * (1.f/B);
        float var = s2 * (1.f/B) - mu*mu;
        float inv = rsqrtf(var + EPS);
        float sc = bn1_s[j]*inv, ofs = bn1_b[j];
        #pragma unroll
        for (int bb = 0; bb < B; bb++) us[bb*H + j] = (xs[bb*H + j] - mu)*sc + ofs;
    }
    __syncthreads();

    {
        int e = tid;
        float a1[B], a2[B];
        #pragma unroll
        for (int bb = 0; bb < B; bb++) { a1[bb] = 0.f; a2[bb] = 0.f; }
        for (int j = 0; j < H; j++) {
            float w1 = Wup1[j*D + e];
            float w2 = Wup2[j*D + e];
            #pragma unroll
            for (int bb = 0; bb < B; bb++) {
                float uv = us[bb*H + j];
                a1[bb] = fmaf(uv, w1, a1[bb]);
                a2[bb] = fmaf(uv, w2, a2[bb]);
            }
        }
        float b1v = bup1[e], b2v = bup2[e];
        #pragma unroll
        for (int bb = 0; bb < B; bb++) {
            float xv = a1[bb] + b1v;
            xins[bb*D + e] = xv;
            g_xin[(t*B + bb)*D + e] = xv;
            float tv = a2[bb] + b2v;
            g_trig[(t*B + bb)*D + e] = tv / (1.f + expf(-tv));
        }
    }
    __syncthreads();

    for (int idx = tid; idx < NH*B*D; idx += 256) {
        int hh = idx / (B*D);
        int rem = idx % (B*D);
        int bb = rem / D, dd = rem % D;
        float acc = convb[hh];
        #pragma unroll
        for (int w = 0; w < 4; w++) {
            int dj = dd - 1 + w;
            if (dj >= 0 && dj < D) acc = fmaf(xins[bb*D + dj], convk[w*NH + hh], acc);
        }
        g_qk[((t*NH + hh)*B + bb)*D + dd] = acc / (1.f + expf(-acc));
    }

    if (tid < 2*HB) {
        int which = tid / HB;
        int p = tid % HB;
        int hh = p / B, bb = p % B;
        const float* W = which ? Wf : Wi;
        float acc = which ? bf[hh] : bi[hh];
        for (int dd = 0; dd < D; dd++) acc = fmaf(xins[bb*D + dd], W[hh*D + dd], acc);
        if (which) g_fpre[t*HB + p] = acc; else g_ipre[t*HB + p] = acc;
    }
}

// ---------------- K2: scalar gate scan ----------------
__global__ void k2_scan()
{
    int p = threadIdx.x;
    if (p >= HB) return;
    float m = 0.f, cf = 0.f;
    for (int t = 0; t < T; t++) {
        float f = g_fpre[t*HB + p];
        float i = g_ipre[t*HB + p];
        cf += f;
        float mn = fmaxf(f + m, i);
        g_ad[t*HB + p] = i - cf;
        g_bd[t*HB + p] = cf - mn;
        m = mn;
    }
}

// ---------------- K3: batched projection GEMMs (vectorized, BK=32) -----------
__global__ __launch_bounds__(256) void k3_gemm(
    const float* __restrict__ Wq, const float* __restrict__ bq,
    const float* __restrict__ Wk, const float* __restrict__ bk,
    const float* __restrict__ Wv, const float* __restrict__ bv,
    const float* __restrict__ Wo, const float* __restrict__ bo,
    const float* __restrict__ Wsk,const float* __restrict__ bsk)
{
    int inst = blockIdx.y;           // 0..19
    int proj = inst / NH;
    int h    = inst % NH;
    int tm = blockIdx.x & 7;
    int tn = blockIdx.x >> 3;

    const float* W; const float* bias; int src;
    switch (proj) {
        case 0: W = Wq;  bias = bq;  src = 0; break;
        case 1: W = Wk;  bias = bk;  src = 0; break;
        case 2: W = Wv;  bias = bv;  src = 1; break;
        case 3: W = Wo;  bias = bo;  src = 1; break;
        default:W = Wsk; bias = bsk; src = 0; break;
    }

    __shared__ float As[32*68];  // k-major: As[c*68 + r]
    __shared__ float Bs[32*68];  // Bs[kr*68 + cc]

    int tid = threadIdx.x;
    int tx = tid & 15;
    int ty = tid >> 4;

    float acc[4][4];
    #pragma unroll
    for (int i = 0; i < 4; i++)
        #pragma unroll
        for (int j = 0; j < 4; j++) acc[i][j] = 0.f;

    const float* Wb = W + (size_t)h*D*D;

    for (int kt = 0; kt < 8; kt++) {
        #pragma unroll
        for (int i = 0; i < 8; i++) {
            int e = tid + 256*i;
            int r = e >> 5, c = e & 31;
            int gr = tm*64 + r;
            int t = gr >> 3, bb = gr & 7;
            int dcol = kt*32 + c;
            float av = (src == 0) ? g_qk[((t*NH + h)*B + bb)*D + dcol]
                                  : g_xin[(t*B + bb)*D + dcol];
            As[c*68 + r] = av;
        }
        #pragma unroll
        for (int i = 0; i < 8; i++) {
            int e = tid + 256*i;
            int kr = e >> 6, cc = e & 63;
            Bs[kr*68 + cc] = Wb[(kt*32 + kr)*D + tn*64 + cc];
        }
        __syncthreads();
        #pragma unroll
        for (int kk = 0; kk < 32; kk++) {
            float4 a4 = *(const float4*)&As[kk*68 + ty*4];
            float4 b4 = *(const float4*)&Bs[kk*68 + tx*4];
            float ar[4] = {a4.x, a4.y, a4.z, a4.w};
            float br[4] = {b4.x, b4.y, b4.z, b4.w};
            #pragma unroll
            for (int i = 0; i < 4; i++)
                #pragma unroll
                for (int j = 0; j < 4; j++) acc[i][j] = fmaf(ar[i], br[j], acc[i][j]);
        }
        __syncthreads();
    }

    #pragma unroll
    for (int i = 0; i < 4; i++) {
        int gr = tm*64 + ty*4 + i;
        int t = gr >> 3, bb = gr & 7;
        #pragma unroll
        for (int j = 0; j < 4; j++) {
            int e = tn*64 + tx*4 + j;
            float v = acc[i][j] + bias[h*D + e];
            size_t oidx = ((size_t)(h*B + bb)*T + t)*D + e;
            switch (proj) {
                case 0: g_q [oidx] = v; break;
                case 1: g_k [oidx] = v * INV_SQRT_D; break;
                case 2: g_v [oidx] = v; break;
                case 3: g_og[oidx] = 1.f / (1.f + expf(-v)); break;
                default:g_sk[oidx] = v; break;
            }
        }
    }
}

// ---------------- K4a: scores S = Q.K^T with decay/mask/rowsum ---------------
// grid (HB, 4): block does t-rows [y*16, y*16+16), all s, K=256
extern __shared__ float sm4a[];
__global__ __launch_bounds__(256) void k4a()
{
    float* Qs  = sm4a;            // 16*256
    float* Kst = sm4a + 16*256;   // e-major: Kst[e*68 + s], 256*68
    __shared__ float ad_s[64];
    __shared__ float bd_s[16];

    int hb = blockIdx.x;
    int yt = blockIdx.y;
    int tid = threadIdx.x;

    const float* Qg = g_q + (size_t)hb*T*D;
    const float* Kg = g_k + (size_t)hb*T*D;

    for (int i = tid; i < 16*256; i += 256) {
        int r = i >> 8, e = i & 255;
        Qs[r*256 + e] = Qg[(yt*16 + r)*D + e];
    }
    for (int i = tid; i < 64*256; i += 256) {
        int s = i >> 8, e = i & 255;
        Kst[e*68 + s] = Kg[s*D + e];
    }
    if (tid < 64) ad_s[tid] = g_ad[tid*HB + hb];
    if (tid < 16) bd_s[tid] = g_bd[(yt*16 + tid)*HB + hb];
    __syncthreads();

    int r  = tid >> 4;            // 0..15 local t row
    int cc = (tid & 15) * 4;      // s columns
    int tq = yt*16 + r;

    float a0 = 0.f, a1 = 0.f, a2 = 0.f, a3 = 0.f;
    for (int e = 0; e < 256; e += 4) {
        float4 q4 = *(const float4*)&Qs[r*256 + e];
        #pragma unroll
        for (int u = 0; u < 4; u++) {
            float qv = (u == 0) ? q4.x : (u == 1) ? q4.y : (u == 2) ? q4.z : q4.w;
            float4 k4 = *(const float4*)&Kst[(e + u)*68 + cc];
            a0 = fmaf(qv, k4.x, a0);
            a1 = fmaf(qv, k4.y, a1);
            a2 = fmaf(qv, k4.z, a2);
            a3 = fmaf(qv, k4.w, a3);
        }
    }

    float bdv = bd_s[r];
    float w0 = (cc + 0 <= tq) ? expf(ad_s[cc + 0] + bdv) * a0 : 0.f;
    float w1 = (cc + 1 <= tq) ? expf(ad_s[cc + 1] + bdv) * a1 : 0.f;
    float w2 = (cc + 2 <= tq) ? expf(ad_s[cc + 2] + bdv) * a2 : 0.f;
    float w3 = (cc + 3 <= tq) ? expf(ad_s[cc + 3] + bdv) * a3 : 0.f;
    float rsum = w0 + w1 + w2 + w3;
    #pragma unroll
    for (int o = 8; o; o >>= 1) rsum += __shfl_xor_sync(0xffffffffu, rsum, o);
    if ((tid & 15) == 0) g_sc[hb*T + tq] = 1.f / fmaxf(fabsf(rsum), 1.f);
    *(float4*)&g_w[((size_t)hb*T + tq)*T + cc] = make_float4(w0, w1, w2, w3);
}

// ---------------- K4b: O = W.V fused with og*scaler + skip -------------------
// grid (HB, 4): block does all 64 t, e-slice [y*64, y*64+64), K = 64 (s)
__global__ __launch_bounds__(256) void k4b()
{
    __shared__ float WsT[64*68];   // s-major: WsT[s*68 + t]
    __shared__ float Vs [64*68];   // Vs[s*68 + el]
    __shared__ float sc_s[64];

    int hb = blockIdx.x;
    int h = hb / B, b = hb % B;
    int eoff = blockIdx.y * 64;
    int tid = threadIdx.x;

    for (int i = tid; i < T*T; i += 256) {
        int t = i >> 6, s = i & 63;
        WsT[s*68 + t] = g_w[((size_t)hb*T + t)*T + s];
    }
    const float* Vg = g_v + (size_t)hb*T*D;
    for (int i = tid; i < 64*64; i += 256) {
        int s = i >> 6, el = i & 63;
        Vs[s*68 + el] = Vg[s*D + eoff + el];
    }
    if (tid < 64) sc_s[tid] = g_sc[hb*T + tid];
    __syncthreads();

    int tx = tid & 15;
    int ty = tid >> 4;

    float acc[4][4];
    #pragma unroll
    for (int i = 0; i < 4; i++)
        #pragma unroll
        for (int j = 0; j < 4; j++) acc[i][j] = 0.f;

    #pragma unroll 4
    for (int s = 0; s < 64; s++) {
        float4 w4 = *(const float4*)&WsT[s*68 + ty*4];
        float4 v4 = *(const float4*)&Vs [s*68 + tx*4];
        float wr[4] = {w4.x, w4.y, w4.z, w4.w};
        float vr[4] = {v4.x, v4.y, v4.z, v4.w};
        #pragma unroll
        for (int i = 0; i < 4; i++)
            #pragma unroll
            for (int j = 0; j < 4; j++) acc[i][j] = fmaf(wr[i], vr[j], acc[i][j]);
    }

    const float* OGg = g_og + (size_t)hb*T*D;
    const float* SKg = g_sk + (size_t)hb*T*D;
    #pragma unroll
    for (int i = 0; i < 4; i++) {
        int t = ty*4 + i;
        float scv = sc_s[t];
        float4 og4 = *(const float4*)&OGg[t*D + eoff + tx*4];
        float4 sk4 = *(const float4*)&SKg[t*D + eoff + tx*4];
        float4 hv;
        hv.x = og4.x * acc[i][0] * scv + sk4.x;
        hv.y = og4.y * acc[i][1] * scv + sk4.y;
        hv.z = og4.z * acc[i][2] * scv + sk4.z;
        hv.w = og4.w * acc[i][3] * scv + sk4.w;
        *(float4*)&g_h[((size_t)(t*NH + h)*B + b)*D + eoff + tx*4] = hv;
    }
}

// ---------------- K5a: BN2 + re-layout to [(t,b)][(h,d)] ---------------------
__global__ __launch_bounds__(256) void k5a(const float* __restrict__ bn2_s,
                                           const float* __restrict__ bn2_b)
{
    int t = blockIdx.x;
    int tid = threadIdx.x;
    __shared__ float hs[32*257];

    for (int i = tid; i < 32*256; i += 256) {
        int p = i >> 8, d = i & 255;
        hs[p*257 + d] = g_h[(size_t)t*NH*B*D + p*256 + d];
    }
    __syncthreads();

    int d = tid;
    float s = 0.f, s2 = 0.f;
    #pragma unroll
    for (int p = 0; p < 32; p++) { float v = hs[p*257 + d]; s += v; s2 += v*v; }
    float mu  = s * (1.f/32);
    float var = s2 * (1.f/32) - mu*mu;
    float inv = rsqrtf(var + EPS);
    float sc = bn2_s[d]*inv, ofs = bn2_b[d];
    #pragma unroll
    for (int p = 0; p < 32; p++) {
        int hh = p >> 3, bb = p & 7;
        g_hn[(size_t)(t*B + bb)*(NH*D) + hh*D + d] = (hs[p*257 + d] - mu)*sc + ofs;
    }
}

// ---------------- K5b: poll GEMM [512,1024]x[1024,256], K-split 2 ------------
__global__ __launch_bounds__(256) void k5b(const float* __restrict__ Wpoll)
{
    int tm = blockIdx.x;   // 0..7 (64-row tiles)
    int tn = blockIdx.y;   // 0..3 (64-col tiles)
    int kz = blockIdx.z;   // 0..1

    __shared__ float As[32*68];
    __shared__ float Bs[32*68];

    int tid = threadIdx.x;
    int tx = tid & 15;
    int ty = tid >> 4;

    float acc[4][4];
    #pragma unroll
    for (int i = 0; i < 4; i++)
        #pragma unroll
        for (int j = 0; j < 4; j++) acc[i][j] = 0.f;

    for (int kt = 0; kt < 16; kt++) {
        int k0 = kz*512 + kt*32;
        #pragma unroll
        for (int i = 0; i < 8; i++) {
            int e = tid + 256*i;
            int r = e >> 5, c = e & 31;
            As[c*68 + r] = g_hn[(size_t)(tm*64 + r)*(NH*D) + k0 + c];
        }
        #pragma unroll
        for (int i = 0; i < 8; i++) {
            int e = tid + 256*i;
            int kr = e >> 6, cc = e & 63;
            Bs[kr*68 + cc] = Wpoll[(size_t)(k0 + kr)*D + tn*64 + cc];
        }
        __syncthreads();
        #pragma unroll
        for (int kk = 0; kk < 32; kk++) {
            float4 a4 = *(const float4*)&As[kk*68 + ty*4];
            float4 b4 = *(const float4*)&Bs[kk*68 + tx*4];
            float ar[4] = {a4.x, a4.y, a4.z, a4.w};
            float br[4] = {b4.x, b4.y, b4.z, b4.w};
            #pragma unroll
            for (int i = 0; i < 4; i++)
                #pragma unroll
                for (int j = 0; j < 4; j++) acc[i][j] = fmaf(ar[i], br[j], acc[i][j]);
        }
        __syncthreads();
    }

    #pragma unroll
    for (int i = 0; i < 4; i++) {
        int row = tm*64 + ty*4 + i;
        *(float4*)&g_pp[(size_t)kz*T*B*D + (size_t)row*D + tn*64 + tx*4] =
            make_float4(acc[i][0], acc[i][1], acc[i][2], acc[i][3]);
    }
}

// ---------------- K5c: combine partials + trig gate + down + residual --------
__global__ __launch_bounds__(256) void k5c(
    const float* __restrict__ x,
    const float* __restrict__ bpoll,
    const float* __restrict__ Wdown, const float* __restrict__ bdown,
    float* __restrict__ out)
{
    int t = blockIdx.x;
    int tid = threadIdx.x;
    __shared__ float ps[B*D];

    for (int i = tid; i < B*D; i += 256) {
        int bb = i >> 8, e = i & 255;
        size_t row = (size_t)(t*B + bb)*D + e;
        float pv = g_pp[row] + g_pp[(size_t)T*B*D + row] + bpoll[e];
        ps[bb*D + e] = pv * g_trig[row];
    }
    __syncthreads();

    int j = tid & 127;
    int bg = tid >> 7;
    float acc[4] = {0.f, 0.f, 0.f, 0.f};
    for (int e = 0; e < D; e++) {
        float w = Wdown[e*H + j];
        #pragma unroll
        for (int q = 0; q < 4; q++) acc[q] = fmaf(ps[(bg*4 + q)*D + e], w, acc[q]);
    }
    #pragma unroll
    for (int q = 0; q < 4; q++) {
        int bb = bg*4 + q;
        out[(t*B + bb)*H + j] = acc[q] + bdown[j] + x[(t*B + bb)*H + j];
    }
}

// ---------------- launch -----------------------------------------------------
extern "C" void kernel_launch(void* const* d_in, const int* in_sizes, int n_in,
                              void* d_out, int out_size)
{
    const float* x      = (const float*)d_in[0];
    const float* Wq     = (const float*)d_in[1];
    const float* bq     = (const float*)d_in[2];
    const float* Wk     = (const float*)d_in[3];
    const float* bk     = (const float*)d_in[4];
    const float* Wv     = (const float*)d_in[5];
    const float* bv     = (const float*)d_in[6];
    const float* convk  = (const float*)d_in[7];
    const float* convb  = (const float*)d_in[8];
    const float* Wi     = (const float*)d_in[9];
    const float* bi     = (const float*)d_in[10];
    const float* Wf     = (const float*)d_in[11];
    const float* bf     = (const float*)d_in[12];
    const float* Wo     = (const float*)d_in[13];
    const float* bo     = (const float*)d_in[14];
    const float* Wsk    = (const float*)d_in[15];
    const float* bsk    = (const float*)d_in[16];
    const float* bn1_s  = (const float*)d_in[17];
    const float* bn1_b  = (const float*)d_in[18];
    const float* bn2_s  = (const float*)d_in[19];
    const float* bn2_b  = (const float*)d_in[20];
    const float* Wup1   = (const float*)d_in[21];
    const float* bup1   = (const float*)d_in[22];
    const float* Wup2   = (const float*)d_in[23];
    const float* bup2   = (const float*)d_in[24];
    const float* Wpoll  = (const float*)d_in[25];
    const float* bpoll  = (const float*)d_in[26];
    const float* Wdown  = (const float*)d_in[27];
    const float* bdown  = (const float*)d_in[28];
    float* out = (float*)d_out;

    static int inited = 0;
    static const int sm4a_bytes = (16*256 + 256*68) * 4;  // ~86KB
    if (!inited) {
        cudaFuncSetAttribute(k4a, cudaFuncAttributeMaxDynamicSharedMemorySize,
                             sm4a_bytes);
        inited = 1;
    }

    k1_pre<<<T, 256>>>(x, bn1_s, bn1_b, Wup1, bup1, Wup2, bup2,
                       convk, convb, Wi, bi, Wf, bf);
    k2_scan<<<1, 32>>>();
    k3_gemm<<<dim3(32, 20), 256>>>(Wq, bq, Wk, bk, Wv, bv, Wo, bo, Wsk, bsk);
    k4a<<<dim3(HB, 4), 256, sm4a_bytes>>>();
    k4b<<<dim3(HB, 4), 256>>>();
    k5a<<<T, 256>>>(bn2_s, bn2_b);
    k5b<<<dim3(8, 4, 2), 256>>>(Wpoll);
    k5c<<<T, 256>>>(x, bpoll, Wdown, bdown, out);
}

// round 6
// speedup vs baseline: 1.6031x; 1.1046x over previous
#include <cuda_runtime.h>
#include <cuda_bf16.h>
#include <cstdint>

// Dims
#define T 64
#define B 8
#define H 128
#define NH 4
#define D 256
#define HB (NH*B)          // 32
#define EPS 1e-5f
#define INV_SQRT_D 0.0625f

// ---------------- scratch (device globals; no allocation) ----------------
__device__ float g_u   [T*B*H];      // BN1 output [(t*B+b)][j]
__device__ float g_xin [T*B*D];
__device__ float g_trig[T*B*D];
__device__ float g_qk  [T*NH*B*D];
__device__ float g_ipre[T*HB];
__device__ float g_fpre[T*HB];
__device__ float g_ad  [T*HB];
__device__ float g_bd  [T*HB];
__device__ float g_q [NH*B*T*D];     // [hb][t][e]
__device__ float g_k [NH*B*T*D];
__device__ float g_v [NH*B*T*D];
__device__ float g_og[NH*B*T*D];
__device__ float g_sk[NH*B*T*D];
__device__ float g_wp[HB*4*T*T];     // score partials [hb][kz][t][s]
__device__ float g_h [T*NH*B*D];     // [t][h][b][d]
__device__ float g_hn[T*B*NH*D];     // BN2'd, [(t*B+b)][h*D+d]
__device__ float g_pp[4*T*B*D];      // poll partials [kz][(t*B+b)][e]

// ---------------- K1a: BN1 ---------------------------------------------------
__global__ __launch_bounds__(128) void k1a(const float* __restrict__ x,
                                           const float* __restrict__ bn1_s,
                                           const float* __restrict__ bn1_b)
{
    int t = blockIdx.x;
    int j = threadIdx.x;  // 128
    float v[B];
    float s = 0.f, s2 = 0.f;
    #pragma unroll
    for (int bb = 0; bb < B; bb++) {
        v[bb] = x[t*B*H + bb*H + j];
        s += v[bb]; s2 += v[bb]*v[bb];
    }
    float mu  = s * (1.f/B);
    float var = s2 * (1.f/B) - mu*mu;
    float inv = rsqrtf(var + EPS);
    float sc = bn1_s[j]*inv, ofs = bn1_b[j];
    #pragma unroll
    for (int bb = 0; bb < B; bb++)
        g_u[(t*B + bb)*H + j] = (v[bb] - mu)*sc + ofs;
}

// ---------------- K1b: up-proj GEMM [512,128] x [128,512] -------------------
// cols 0..255 -> g_xin (+bup1), cols 256..511 -> silu -> g_trig (+bup2)
__global__ __launch_bounds__(256) void k1b(const float* __restrict__ Wup1,
                                           const float* __restrict__ bup1,
                                           const float* __restrict__ Wup2,
                                           const float* __restrict__ bup2)
{
    int tm = blockIdx.x;   // 0..7
    int tn = blockIdx.y;   // 0..7 (cols of concat 512)

    __shared__ float As[32*68];  // k-major As[c*68 + r]
    __shared__ float Bs[32*68];

    int tid = threadIdx.x;
    int tx = tid & 15;
    int ty = tid >> 4;

    float acc[4][4];
    #pragma unroll
    for (int i = 0; i < 4; i++)
        #pragma unroll
        for (int j = 0; j < 4; j++) acc[i][j] = 0.f;

    for (int kt = 0; kt < 4; kt++) {
        #pragma unroll
        for (int i = 0; i < 8; i++) {
            int e = tid + 256*i;
            int r = e >> 5, c = e & 31;
            As[c*68 + r] = g_u[(tm*64 + r)*H + kt*32 + c];
        }
        #pragma unroll
        for (int i = 0; i < 8; i++) {
            int e = tid + 256*i;
            int kr = e >> 6, cc = e & 63;
            int jrow = kt*32 + kr;
            int col = tn*64 + cc;
            float w = (col < 256) ? Wup1[jrow*D + col] : Wup2[jrow*D + col - 256];
            Bs[kr*68 + cc] = w;
        }
        __syncthreads();
        #pragma unroll
        for (int kk = 0; kk < 32; kk++) {
            float4 a4 = *(const float4*)&As[kk*68 + ty*4];
            float4 b4 = *(const float4*)&Bs[kk*68 + tx*4];
            float ar[4] = {a4.x, a4.y, a4.z, a4.w};
            float br[4] = {b4.x, b4.y, b4.z, b4.w};
            #pragma unroll
            for (int i = 0; i < 4; i++)
                #pragma unroll
                for (int j = 0; j < 4; j++) acc[i][j] = fmaf(ar[i], br[j], acc[i][j]);
        }
        __syncthreads();
    }

    bool istrig = (tn >= 4);
    #pragma unroll
    for (int i = 0; i < 4; i++) {
        int row = tm*64 + ty*4 + i;
        int col = tn*64 + tx*4;
        if (!istrig) {
            float4 o;
            o.x = acc[i][0] + bup1[col+0];
            o.y = acc[i][1] + bup1[col+1];
            o.z = acc[i][2] + bup1[col+2];
            o.w = acc[i][3] + bup1[col+3];
            *(float4*)&g_xin[(size_t)row*D + col] = o;
        } else {
            int c2 = col - 256;
            float4 o;
            float tv;
            tv = acc[i][0] + bup2[c2+0]; o.x = tv / (1.f + expf(-tv));
            tv = acc[i][1] + bup2[c2+1]; o.y = tv / (1.f + expf(-tv));
            tv = acc[i][2] + bup2[c2+2]; o.z = tv / (1.f + expf(-tv));
            tv = acc[i][3] + bup2[c2+3]; o.w = tv / (1.f + expf(-tv));
            *(float4*)&g_trig[(size_t)row*D + c2] = o;
        }
    }
}

// ---------------- K1c: conv/qk + gate pre-acts -------------------------------
__global__ __launch_bounds__(256) void k1c(const float* __restrict__ convk,
                                           const float* __restrict__ convb,
                                           const float* __restrict__ Wi,
                                           const float* __restrict__ bi,
                                           const float* __restrict__ Wf,
                                           const float* __restrict__ bf)
{
    int t = blockIdx.x;
    int tid = threadIdx.x;
    __shared__ float xins[B*D];

    for (int i = tid; i < B*D; i += 256) xins[i] = g_xin[(size_t)t*B*D + i];
    __syncthreads();

    // conv (SAME k=4, pad_left=1) + silu
    for (int idx = tid; idx < NH*B*D; idx += 256) {
        int hh = idx / (B*D);
        int rem = idx % (B*D);
        int bb = rem / D, dd = rem % D;
        float acc = convb[hh];
        #pragma unroll
        for (int w = 0; w < 4; w++) {
            int dj = dd - 1 + w;
            if (dj >= 0 && dj < D) acc = fmaf(xins[bb*D + dj], convk[w*NH + hh], acc);
        }
        g_qk[((t*NH + hh)*B + bb)*D + dd] = acc / (1.f + expf(-acc));
    }

    // gates: 64 dots of length 256, 4-lane groups
    {
        int g = tid >> 2;          // 0..63 dot id
        int r = tid & 3;           // lane in group
        int which = g >> 5;        // 0=i, 1=f
        int p = g & 31;            // h*B+b
        int hh = p >> 3, bb = p & 7;
        const float* W = which ? (Wf + hh*D) : (Wi + hh*D);
        const float* xb = xins + bb*D;
        float acc = 0.f;
        for (int u = 0; u < 64; u++) {
            int dd = r + 4*u;
            acc = fmaf(xb[dd], W[dd], acc);
        }
        acc += __shfl_xor_sync(0xffffffffu, acc, 1);
        acc += __shfl_xor_sync(0xffffffffu, acc, 2);
        if (r == 0) {
            if (which) g_fpre[t*HB + p] = acc + bf[hh];
            else       g_ipre[t*HB + p] = acc + bi[hh];
        }
    }
}

// ---------------- K2: scalar gate scan ----------------
__global__ void k2_scan()
{
    int p = threadIdx.x;
    if (p >= HB) return;
    float m = 0.f, cf = 0.f;
    for (int t = 0; t < T; t++) {
        float f = g_fpre[t*HB + p];
        float i = g_ipre[t*HB + p];
        cf += f;
        float mn = fmaxf(f + m, i);
        g_ad[t*HB + p] = i - cf;
        g_bd[t*HB + p] = cf - mn;
        m = mn;
    }
}

// ---------------- K3: batched projection GEMMs (128x64 tiles) ----------------
// 20 instances: C[512,256] = A[512,256] @ W[h][256,256]
__global__ __launch_bounds__(256) void k3_gemm(
    const float* __restrict__ Wq, const float* __restrict__ bq,
    const float* __restrict__ Wk, const float* __restrict__ bk,
    const float* __restrict__ Wv, const float* __restrict__ bv,
    const float* __restrict__ Wo, const float* __restrict__ bo,
    const float* __restrict__ Wsk,const float* __restrict__ bsk)
{
    int inst = blockIdx.y;           // 0..19
    int proj = inst / NH;
    int h    = inst % NH;
    int tm = blockIdx.x & 3;         // 4 M tiles of 128
    int tn = blockIdx.x >> 2;        // 4 N tiles of 64

    const float* W; const float* bias; int src;
    switch (proj) {
        case 0: W = Wq;  bias = bq;  src = 0; break;
        case 1: W = Wk;  bias = bk;  src = 0; break;
        case 2: W = Wv;  bias = bv;  src = 1; break;
        case 3: W = Wo;  bias = bo;  src = 1; break;
        default:W = Wsk; bias = bsk; src = 0; break;
    }

    __shared__ float As[32*132];  // k-major: As[c*132 + r], r<128
    __shared__ float Bs[32*68];

    int tid = threadIdx.x;
    int tx = tid & 15;
    int ty = tid >> 4;

    float acc[8][4];
    #pragma unroll
    for (int i = 0; i < 8; i++)
        #pragma unroll
        for (int j = 0; j < 4; j++) acc[i][j] = 0.f;

    const float* Wb = W + (size_t)h*D*D;

    for (int kt = 0; kt < 8; kt++) {
        #pragma unroll
        for (int i = 0; i < 16; i++) {
            int e = tid + 256*i;
            int r = e >> 5, c = e & 31;
            int gr = tm*128 + r;
            int t = gr >> 3, bb = gr & 7;
            int dcol = kt*32 + c;
            float av = (src == 0) ? g_qk[((t*NH + h)*B + bb)*D + dcol]
                                  : g_xin[(t*B + bb)*D + dcol];
            As[c*132 + r] = av;
        }
        #pragma unroll
        for (int i = 0; i < 8; i++) {
            int e = tid + 256*i;
            int kr = e >> 6, cc = e & 63;
            Bs[kr*68 + cc] = Wb[(kt*32 + kr)*D + tn*64 + cc];
        }
        __syncthreads();
        #pragma unroll
        for (int kk = 0; kk < 32; kk++) {
            float4 a0 = *(const float4*)&As[kk*132 + ty*8];
            float4 a1 = *(const float4*)&As[kk*132 + ty*8 + 4];
            float4 b4 = *(const float4*)&Bs[kk*68 + tx*4];
            float ar[8] = {a0.x, a0.y, a0.z, a0.w, a1.x, a1.y, a1.z, a1.w};
            float br[4] = {b4.x, b4.y, b4.z, b4.w};
            #pragma unroll
            for (int i = 0; i < 8; i++)
                #pragma unroll
                for (int j = 0; j < 4; j++) acc[i][j] = fmaf(ar[i], br[j], acc[i][j]);
        }
        __syncthreads();
    }

    #pragma unroll
    for (int i = 0; i < 8; i++) {
        int gr = tm*128 + ty*8 + i;
        int t = gr >> 3, bb = gr & 7;
        #pragma unroll
        for (int j = 0; j < 4; j++) {
            int e = tn*64 + tx*4 + j;
            float v = acc[i][j] + bias[h*D + e];
            size_t oidx = ((size_t)(h*B + bb)*T + t)*D + e;
            switch (proj) {
                case 0: g_q [oidx] = v; break;
                case 1: g_k [oidx] = v * INV_SQRT_D; break;
                case 2: g_v [oidx] = v; break;
                case 3: g_og[oidx] = 1.f / (1.f + expf(-v)); break;
                default:g_sk[oidx] = v; break;
            }
        }
    }
}

// ---------------- K4a: score partials, split-K over e ------------------------
// grid (HB, 4): partial[t][s] = sum_{e in quarter} Q[t][e]*K[s][e]
__global__ __launch_bounds__(256) void k4a()
{
    __shared__ float As[16*68];   // [c][t]
    __shared__ float Bs[16*68];   // [c][s]

    int hb = blockIdx.x;
    int kz = blockIdx.y;
    int tid = threadIdx.x;
    int tx = tid & 15;
    int ty = tid >> 4;

    const float* Qg = g_q + (size_t)hb*T*D + kz*64;
    const float* Kg = g_k + (size_t)hb*T*D + kz*64;

    float acc[4][4];
    #pragma unroll
    for (int i = 0; i < 4; i++)
        #pragma unroll
        for (int j = 0; j < 4; j++) acc[i][j] = 0.f;

    for (int ch = 0; ch < 4; ch++) {
        #pragma unroll
        for (int i = 0; i < 4; i++) {
            int e = tid + 256*i;
            int r = e >> 4, c = e & 15;
            As[c*68 + r] = Qg[r*D + ch*16 + c];
            Bs[c*68 + r] = Kg[r*D + ch*16 + c];
        }
        __syncthreads();
        #pragma unroll
        for (int kk = 0; kk < 16; kk++) {
            float4 a4 = *(const float4*)&As[kk*68 + ty*4];
            float4 b4 = *(const float4*)&Bs[kk*68 + tx*4];
            float ar[4] = {a4.x, a4.y, a4.z, a4.w};
            float br[4] = {b4.x, b4.y, b4.z, b4.w};
            #pragma unroll
            for (int i = 0; i < 4; i++)
                #pragma unroll
                for (int j = 0; j < 4; j++) acc[i][j] = fmaf(ar[i], br[j], acc[i][j]);
        }
        __syncthreads();
    }

    float* out = g_wp + ((size_t)(hb*4 + kz))*T*T;
    #pragma unroll
    for (int i = 0; i < 4; i++)
        *(float4*)&out[(ty*4 + i)*T + tx*4] =
            make_float4(acc[i][0], acc[i][1], acc[i][2], acc[i][3]);
}

// ---------------- K4b: combine + decay/mask/rowsum + O=W.V fused -------------
// grid (HB, 4): all 64 t, e-slice [y*64, y*64+64)
__global__ __launch_bounds__(256) void k4b()
{
    __shared__ float WsT[64*68];   // s-major: WsT[s*68 + t]
    __shared__ float Vs [64*68];
    __shared__ float sc_s[64];
    __shared__ float ad_s[64];
    __shared__ float bd_s[64];

    int hb = blockIdx.x;
    int h = hb / B, b = hb % B;
    int eoff = blockIdx.y * 64;
    int tid = threadIdx.x;

    if (tid < 64) {
        ad_s[tid] = g_ad[tid*HB + hb];
        bd_s[tid] = g_bd[tid*HB + hb];
    }
    __syncthreads();

    const float* wp = g_wp + (size_t)hb*4*T*T;
    for (int i = tid; i < T*T; i += 256) {
        int t = i >> 6, s = i & 63;
        float p = wp[i] + wp[T*T + i] + wp[2*T*T + i] + wp[3*T*T + i];
        float w = (s <= t) ? expf(ad_s[s] + bd_s[t]) * p : 0.f;
        WsT[s*68 + t] = w;
    }
    const float* Vg = g_v + (size_t)hb*T*D;
    for (int i = tid; i < 64*64; i += 256) {
        int s = i >> 6, el = i & 63;
        Vs[s*68 + el] = Vg[s*D + eoff + el];
    }
    __syncthreads();

    if (tid < 64) {
        float r = 0.f;
        #pragma unroll 8
        for (int s = 0; s < 64; s++) r += WsT[s*68 + tid];
        sc_s[tid] = 1.f / fmaxf(fabsf(r), 1.f);
    }
    __syncthreads();

    int tx = tid & 15;
    int ty = tid >> 4;

    float acc[4][4];
    #pragma unroll
    for (int i = 0; i < 4; i++)
        #pragma unroll
        for (int j = 0; j < 4; j++) acc[i][j] = 0.f;

    #pragma unroll 4
    for (int s = 0; s < 64; s++) {
        float4 w4 = *(const float4*)&WsT[s*68 + ty*4];
        float4 v4 = *(const float4*)&Vs [s*68 + tx*4];
        float wr[4] = {w4.x, w4.y, w4.z, w4.w};
        float vr[4] = {v4.x, v4.y, v4.z, v4.w};
        #pragma unroll
        for (int i = 0; i < 4; i++)
            #pragma unroll
            for (int j = 0; j < 4; j++) acc[i][j] = fmaf(wr[i], vr[j], acc[i][j]);
    }

    const float* OGg = g_og + (size_t)hb*T*D;
    const float* SKg = g_sk + (size_t)hb*T*D;
    #pragma unroll
    for (int i = 0; i < 4; i++) {
        int t = ty*4 + i;
        float scv = sc_s[t];
        float4 og4 = *(const float4*)&OGg[t*D + eoff + tx*4];
        float4 sk4 = *(const float4*)&SKg[t*D + eoff + tx*4];
        float4 hv;
        hv.x = og4.x * acc[i][0] * scv + sk4.x;
        hv.y = og4.y * acc[i][1] * scv + sk4.y;
        hv.z = og4.z * acc[i][2] * scv + sk4.z;
        hv.w = og4.w * acc[i][3] * scv + sk4.w;
        *(float4*)&g_h[((size_t)(t*NH + h)*B + b)*D + eoff + tx*4] = hv;
    }
}

// ---------------- K5a: BN2 + re-layout to [(t,b)][(h,d)] ---------------------
__global__ __launch_bounds__(256) void k5a(const float* __restrict__ bn2_s,
                                           const float* __restrict__ bn2_b)
{
    int t = blockIdx.x;
    int tid = threadIdx.x;
    __shared__ float hs[32*257];

    for (int i = tid; i < 32*256; i += 256) {
        int p = i >> 8, d = i & 255;
        hs[p*257 + d] = g_h[(size_t)t*NH*B*D + p*256 + d];
    }
    __syncthreads();

    int d = tid;
    float s = 0.f, s2 = 0.f;
    #pragma unroll
    for (int p = 0; p < 32; p++) { float v = hs[p*257 + d]; s += v; s2 += v*v; }
    float mu  = s * (1.f/32);
    float var = s2 * (1.f/32) - mu*mu;
    float inv = rsqrtf(var + EPS);
    float sc = bn2_s[d]*inv, ofs = bn2_b[d];
    #pragma unroll
    for (int p = 0; p < 32; p++) {
        int hh = p >> 3, bb = p & 7;
        g_hn[(size_t)(t*B + bb)*(NH*D) + hh*D + d] = (hs[p*257 + d] - mu)*sc + ofs;
    }
}

// ---------------- K5b: poll GEMM [512,1024]x[1024,256], K-split 4 ------------
__global__ __launch_bounds__(256) void k5b(const float* __restrict__ Wpoll)
{
    int tm = blockIdx.x;   // 0..7
    int tn = blockIdx.y;   // 0..3
    int kz = blockIdx.z;   // 0..3

    __shared__ float As[32*68];
    __shared__ float Bs[32*68];

    int tid = threadIdx.x;
    int tx = tid & 15;
    int ty = tid >> 4;

    float acc[4][4];
    #pragma unroll
    for (int i = 0; i < 4; i++)
        #pragma unroll
        for (int j = 0; j < 4; j++) acc[i][j] = 0.f;

    for (int kt = 0; kt < 8; kt++) {
        int k0 = kz*256 + kt*32;
        #pragma unroll
        for (int i = 0; i < 8; i++) {
            int e = tid + 256*i;
            int r = e >> 5, c = e & 31;
            As[c*68 + r] = g_hn[(size_t)(tm*64 + r)*(NH*D) + k0 + c];
        }
        #pragma unroll
        for (int i = 0; i < 8; i++) {
            int e = tid + 256*i;
            int kr = e >> 6, cc = e & 63;
            Bs[kr*68 + cc] = Wpoll[(size_t)(k0 + kr)*D + tn*64 + cc];
        }
        __syncthreads();
        #pragma unroll
        for (int kk = 0; kk < 32; kk++) {
            float4 a4 = *(const float4*)&As[kk*68 + ty*4];
            float4 b4 = *(const float4*)&Bs[kk*68 + tx*4];
            float ar[4] = {a4.x, a4.y, a4.z, a4.w};
            float br[4] = {b4.x, b4.y, b4.z, b4.w};
            #pragma unroll
            for (int i = 0; i < 4; i++)
                #pragma unroll
                for (int j = 0; j < 4; j++) acc[i][j] = fmaf(ar[i], br[j], acc[i][j]);
        }
        __syncthreads();
    }

    #pragma unroll
    for (int i = 0; i < 4; i++) {
        int row = tm*64 + ty*4 + i;
        *(float4*)&g_pp[(size_t)kz*T*B*D + (size_t)row*D + tn*64 + tx*4] =
            make_float4(acc[i][0], acc[i][1], acc[i][2], acc[i][3]);
    }
}

// ---------------- K5c: combine partials + trig gate + down + residual --------
__global__ __launch_bounds__(256) void k5c(
    const float* __restrict__ x,
    const float* __restrict__ bpoll,
    const float* __restrict__ Wdown, const float* __restrict__ bdown,
    float* __restrict__ out)
{
    int t = blockIdx.x;
    int tid = threadIdx.x;
    __shared__ float ps[B*D];

    for (int i = tid; i < B*D; i += 256) {
        int bb = i >> 8, e = i & 255;
        size_t row = (size_t)(t*B + bb)*D + e;
        float pv = g_pp[row] + g_pp[(size_t)T*B*D + row]
                 + g_pp[(size_t)2*T*B*D + row] + g_pp[(size_t)3*T*B*D + row]
                 + bpoll[e];
        ps[bb*D + e] = pv * g_trig[row];
    }
    __syncthreads();

    int j = tid & 127;
    int bg = tid >> 7;
    float acc[4] = {0.f, 0.f, 0.f, 0.f};
    for (int e = 0; e < D; e++) {
        float w = Wdown[e*H + j];
        #pragma unroll
        for (int q = 0; q < 4; q++) acc[q] = fmaf(ps[(bg*4 + q)*D + e], w, acc[q]);
    }
    #pragma unroll
    for (int q = 0; q < 4; q++) {
        int bb = bg*4 + q;
        out[(t*B + bb)*H + j] = acc[q] + bdown[j] + x[(t*B + bb)*H + j];
    }
}

// ---------------- launch -----------------------------------------------------
extern "C" void kernel_launch(void* const* d_in, const int* in_sizes, int n_in,
                              void* d_out, int out_size)
{
    const float* x      = (const float*)d_in[0];
    const float* Wq     = (const float*)d_in[1];
    const float* bq     = (const float*)d_in[2];
    const float* Wk     = (const float*)d_in[3];
    const float* bk     = (const float*)d_in[4];
    const float* Wv     = (const float*)d_in[5];
    const float* bv     = (const float*)d_in[6];
    const float* convk  = (const float*)d_in[7];
    const float* convb  = (const float*)d_in[8];
    const float* Wi     = (const float*)d_in[9];
    const float* bi     = (const float*)d_in[10];
    const float* Wf     = (const float*)d_in[11];
    const float* bf     = (const float*)d_in[12];
    const float* Wo     = (const float*)d_in[13];
    const float* bo     = (const float*)d_in[14];
    const float* Wsk    = (const float*)d_in[15];
    const float* bsk    = (const float*)d_in[16];
    const float* bn1_s  = (const float*)d_in[17];
    const float* bn1_b  = (const float*)d_in[18];
    const float* bn2_s  = (const float*)d_in[19];
    const float* bn2_b  = (const float*)d_in[20];
    const float* Wup1   = (const float*)d_in[21];
    const float* bup1   = (const float*)d_in[22];
    const float* Wup2   = (const float*)d_in[23];
    const float* bup2   = (const float*)d_in[24];
    const float* Wpoll  = (const float*)d_in[25];
    const float* bpoll  = (const float*)d_in[26];
    const float* Wdown  = (const float*)d_in[27];
    const float* bdown  = (const float*)d_in[28];
    float* out = (float*)d_out;

    k1a<<<T, 128>>>(x, bn1_s, bn1_b);
    k1b<<<dim3(8, 8), 256>>>(Wup1, bup1, Wup2, bup2);
    k1c<<<T, 256>>>(convk, convb, Wi, bi, Wf, bf);
    k2_scan<<<1, 32>>>();
    k3_gemm<<<dim3(16, 20), 256>>>(Wq, bq, Wk, bk, Wv, bv, Wo, bo, Wsk, bsk);
    k4a<<<dim3(HB, 4), 256>>>();
    k4b<<<dim3(HB, 4), 256>>>();
    k5a<<<T, 256>>>(bn2_s, bn2_b);
    k5b<<<dim3(8, 4, 4), 256>>>(Wpoll);
    k5c<<<T, 256>>>(x, bpoll, Wdown, bdown, out);
}

// round 8
// speedup vs baseline: 1.8479x; 1.1526x over previous
#include <cuda_runtime.h>
#include <cuda_bf16.h>
#include <cstdint>

// Dims
#define T 64
#define B 8
#define H 128
#define NH 4
#define D 256
#define HB (NH*B)          // 32
#define EPS 1e-5f
#define INV_SQRT_D 0.0625f

typedef unsigned long long u64;

// ---- packed f32x2 helpers (SASS FFMA2: 2 fp32 FMA per fma-pipe slot) --------
__device__ __forceinline__ u64 pack2(float x, float y) {
    u64 r; asm("mov.b64 %0, {%1,%2};" : "=l"(r) : "f"(x), "f"(y)); return r;
}
__device__ __forceinline__ u64 bcast2(float x) {
    u64 r; asm("mov.b64 %0, {%1,%1};" : "=l"(r) : "f"(x)); return r;
}
__device__ __forceinline__ void ffma2(u64& d, u64 a, u64 b) {
    asm("fma.rn.f32x2 %0, %1, %2, %3;" : "=l"(d) : "l"(a), "l"(b), "l"(d));
}
__device__ __forceinline__ float2 unpack2(u64 v) {
    float x, y; asm("mov.b64 {%0,%1}, %2;" : "=f"(x), "=f"(y) : "l"(v));
    return make_float2(x, y);
}

// ---------------- scratch (device globals; no allocation) ----------------
__device__ float g_u   [T*B*H];      // BN1 output [(t*B+b)][j]
__device__ float g_xin [T*B*D];
__device__ float g_trig[T*B*D];
__device__ float g_qk  [T*NH*B*D];
__device__ float g_ipre[T*HB];
__device__ float g_fpre[T*HB];
__device__ float g_ad  [T*HB];
__device__ float g_bd  [T*HB];
__device__ float g_q [NH*B*T*D];     // [hb][t][e]
__device__ float g_k [NH*B*T*D];
__device__ float g_v [NH*B*T*D];
__device__ float g_og[NH*B*T*D];
__device__ float g_sk[NH*B*T*D];
__device__ float g_wp[HB*4*T*T];     // score partials [hb][kz][t][s]
__device__ float g_h [T*NH*B*D];     // [t][h][b][d]
__device__ float g_hn[T*B*NH*D];     // BN2'd, [(t*B+b)][h*D+d]
__device__ float g_pp[4*T*B*D];      // poll partials [kz][(t*B+b)][e]

// ---------------- K1a: BN1 ---------------------------------------------------
__global__ __launch_bounds__(128) void k1a(const float* __restrict__ x,
                                           const float* __restrict__ bn1_s,
                                           const float* __restrict__ bn1_b)
{
    int t = blockIdx.x;
    int j = threadIdx.x;  // 128
    float v[B];
    float s = 0.f, s2 = 0.f;
    #pragma unroll
    for (int bb = 0; bb < B; bb++) {
        v[bb] = x[t*B*H + bb*H + j];
        s += v[bb]; s2 += v[bb]*v[bb];
    }
    float mu  = s * (1.f/B);
    float var = s2 * (1.f/B) - mu*mu;
    float inv = rsqrtf(var + EPS);
    float sc = bn1_s[j]*inv, ofs = bn1_b[j];
    #pragma unroll
    for (int bb = 0; bb < B; bb++)
        g_u[(t*B + bb)*H + j] = (v[bb] - mu)*sc + ofs;
}

// ---------------- K1b: up-proj GEMM [512,128] x [128,512] -------------------
__global__ __launch_bounds__(256) void k1b(const float* __restrict__ Wup1,
                                           const float* __restrict__ bup1,
                                           const float* __restrict__ Wup2,
                                           const float* __restrict__ bup2)
{
    int tm = blockIdx.x;   // 0..7
    int tn = blockIdx.y;   // 0..7

    __shared__ float As[32*68];
    __shared__ float Bs[32*68];

    int tid = threadIdx.x;
    int tx = tid & 15;
    int ty = tid >> 4;

    u64 acc2[2][4];
    #pragma unroll
    for (int i = 0; i < 2; i++)
        #pragma unroll
        for (int j = 0; j < 4; j++) acc2[i][j] = 0ull;

    for (int kt = 0; kt < 4; kt++) {
        #pragma unroll
        for (int i = 0; i < 8; i++) {
            int e = tid + 256*i;
            int r = e >> 5, c = e & 31;
            As[c*68 + r] = g_u[(tm*64 + r)*H + kt*32 + c];
        }
        #pragma unroll
        for (int i = 0; i < 8; i++) {
            int e = tid + 256*i;
            int kr = e >> 6, cc = e & 63;
            int jrow = kt*32 + kr;
            int col = tn*64 + cc;
            float w = (col < 256) ? Wup1[jrow*D + col] : Wup2[jrow*D + col - 256];
            Bs[kr*68 + cc] = w;
        }
        __syncthreads();
        #pragma unroll
        for (int kk = 0; kk < 32; kk++) {
            float4 a4 = *(const float4*)&As[kk*68 + ty*4];
            float4 b4 = *(const float4*)&Bs[kk*68 + tx*4];
            u64 ap[2] = {pack2(a4.x, a4.y), pack2(a4.z, a4.w)};
            u64 bb[4] = {bcast2(b4.x), bcast2(b4.y), bcast2(b4.z), bcast2(b4.w)};
            #pragma unroll
            for (int i = 0; i < 2; i++)
                #pragma unroll
                for (int j = 0; j < 4; j++) ffma2(acc2[i][j], ap[i], bb[j]);
        }
        __syncthreads();
    }

    bool istrig = (tn >= 4);
    #pragma unroll
    for (int ip = 0; ip < 2; ip++) {
        #pragma unroll
        for (int half = 0; half < 2; half++) {
            int row = tm*64 + ty*4 + ip*2 + half;
            int col = tn*64 + tx*4;
            float rv[4];
            #pragma unroll
            for (int j = 0; j < 4; j++) {
                float2 p = unpack2(acc2[ip][j]);
                rv[j] = half ? p.y : p.x;
            }
            if (!istrig) {
                float4 o;
                o.x = rv[0] + bup1[col+0];
                o.y = rv[1] + bup1[col+1];
                o.z = rv[2] + bup1[col+2];
                o.w = rv[3] + bup1[col+3];
                *(float4*)&g_xin[(size_t)row*D + col] = o;
            } else {
                int c2 = col - 256;
                float4 o; float tv;
                tv = rv[0] + bup2[c2+0]; o.x = tv / (1.f + expf(-tv));
                tv = rv[1] + bup2[c2+1]; o.y = tv / (1.f + expf(-tv));
                tv = rv[2] + bup2[c2+2]; o.z = tv / (1.f + expf(-tv));
                tv = rv[3] + bup2[c2+3]; o.w = tv / (1.f + expf(-tv));
                *(float4*)&g_trig[(size_t)row*D + c2] = o;
            }
        }
    }
}

// ---------------- K1c: conv/qk + gate pre-acts -------------------------------
__global__ __launch_bounds__(256) void k1c(const float* __restrict__ convk,
                                           const float* __restrict__ convb,
                                           const float* __restrict__ Wi,
                                           const float* __restrict__ bi,
                                           const float* __restrict__ Wf,
                                           const float* __restrict__ bf)
{
    int t = blockIdx.x;
    int tid = threadIdx.x;
    __shared__ float xins[B*D];

    for (int i = tid; i < B*D; i += 256) xins[i] = g_xin[(size_t)t*B*D + i];
    __syncthreads();

    for (int idx = tid; idx < NH*B*D; idx += 256) {
        int hh = idx / (B*D);
        int rem = idx % (B*D);
        int bb = rem / D, dd = rem % D;
        float acc = convb[hh];
        #pragma unroll
        for (int w = 0; w < 4; w++) {
            int dj = dd - 1 + w;
            if (dj >= 0 && dj < D) acc = fmaf(xins[bb*D + dj], convk[w*NH + hh], acc);
        }
        g_qk[((t*NH + hh)*B + bb)*D + dd] = acc / (1.f + expf(-acc));
    }

    {
        int g = tid >> 2;
        int r = tid & 3;
        int which = g >> 5;
        int p = g & 31;
        int hh = p >> 3, bb = p & 7;
        const float* W = which ? (Wf + hh*D) : (Wi + hh*D);
        const float* xb = xins + bb*D;
        float acc = 0.f;
        for (int u = 0; u < 64; u++) {
            int dd = r + 4*u;
            acc = fmaf(xb[dd], W[dd], acc);
        }
        acc += __shfl_xor_sync(0xffffffffu, acc, 1);
        acc += __shfl_xor_sync(0xffffffffu, acc, 2);
        if (r == 0) {
            if (which) g_fpre[t*HB + p] = acc + bf[hh];
            else       g_ipre[t*HB + p] = acc + bi[hh];
        }
    }
}

// ---------------- K2: gate scan, smem-staged ---------------------------------
__global__ __launch_bounds__(256) void k2_scan()
{
    __shared__ float si[T*HB];   // 8KB, becomes bd
    __shared__ float sf[T*HB];   // 8KB, becomes ad
    int tid = threadIdx.x;

    for (int i = tid; i < T*HB; i += 256) { si[i] = g_ipre[i]; sf[i] = g_fpre[i]; }
    __syncthreads();

    if (tid < HB) {
        int p = tid;
        float m = 0.f, cf = 0.f;
        #pragma unroll
        for (int t = 0; t < T; t++) {
            float f = sf[t*HB + p];
            float i = si[t*HB + p];
            cf += f;
            float mn = fmaxf(f + m, i);
            sf[t*HB + p] = i - cf;    // ad
            si[t*HB + p] = cf - mn;   // bd
            m = mn;
        }
    }
    __syncthreads();

    for (int i = tid; i < T*HB; i += 256) { g_ad[i] = sf[i]; g_bd[i] = si[i]; }
}

// ---------------- K3: batched projection GEMMs (128x64, FFMA2) ---------------
__global__ __launch_bounds__(256) void k3_gemm(
    const float* __restrict__ Wq, const float* __restrict__ bq,
    const float* __restrict__ Wk, const float* __restrict__ bk,
    const float* __restrict__ Wv, const float* __restrict__ bv,
    const float* __restrict__ Wo, const float* __restrict__ bo,
    const float* __restrict__ Wsk,const float* __restrict__ bsk)
{
    int inst = blockIdx.y;           // 0..19
    int proj = inst / NH;
    int h    = inst % NH;
    int tm = blockIdx.x & 3;
    int tn = blockIdx.x >> 2;

    const float* W; const float* bias; int src;
    switch (proj) {
        case 0: W = Wq;  bias = bq;  src = 0; break;
        case 1: W = Wk;  bias = bk;  src = 0; break;
        case 2: W = Wv;  bias = bv;  src = 1; break;
        case 3: W = Wo;  bias = bo;  src = 1; break;
        default:W = Wsk; bias = bsk; src = 0; break;
    }

    __shared__ float As[32*132];
    __shared__ float Bs[32*68];

    int tid = threadIdx.x;
    int tx = tid & 15;
    int ty = tid >> 4;

    u64 acc2[4][4];
    #pragma unroll
    for (int i = 0; i < 4; i++)
        #pragma unroll
        for (int j = 0; j < 4; j++) acc2[i][j] = 0ull;

    const float* Wb = W + (size_t)h*D*D;

    for (int kt = 0; kt < 8; kt++) {
        #pragma unroll
        for (int i = 0; i < 16; i++) {
            int e = tid + 256*i;
            int r = e >> 5, c = e & 31;
            int gr = tm*128 + r;
            int t = gr >> 3, bb = gr & 7;
            int dcol = kt*32 + c;
            float av = (src == 0) ? g_qk[((t*NH + h)*B + bb)*D + dcol]
                                  : g_xin[(t*B + bb)*D + dcol];
            As[c*132 + r] = av;
        }
        #pragma unroll
        for (int i = 0; i < 8; i++) {
            int e = tid + 256*i;
            int kr = e >> 6, cc = e & 63;
            Bs[kr*68 + cc] = Wb[(kt*32 + kr)*D + tn*64 + cc];
        }
        __syncthreads();
        #pragma unroll
        for (int kk = 0; kk < 32; kk++) {
            float4 a0 = *(const float4*)&As[kk*132 + ty*8];
            float4 a1 = *(const float4*)&As[kk*132 + ty*8 + 4];
            float4 b4 = *(const float4*)&Bs[kk*68 + tx*4];
            u64 ap[4] = {pack2(a0.x,a0.y), pack2(a0.z,a0.w),
                         pack2(a1.x,a1.y), pack2(a1.z,a1.w)};
            u64 bb2[4] = {bcast2(b4.x), bcast2(b4.y), bcast2(b4.z), bcast2(b4.w)};
            #pragma unroll
            for (int i = 0; i < 4; i++)
                #pragma unroll
                for (int j = 0; j < 4; j++) ffma2(acc2[i][j], ap[i], bb2[j]);
        }
        __syncthreads();
    }

    #pragma unroll
    for (int ip = 0; ip < 4; ip++) {
        #pragma unroll
        for (int half = 0; half < 2; half++) {
            int gr = tm*128 + ty*8 + ip*2 + half;
            int t = gr >> 3, bb = gr & 7;
            #pragma unroll
            for (int j = 0; j < 4; j++) {
                float2 pr = unpack2(acc2[ip][j]);
                float v = (half ? pr.y : pr.x);
                int e = tn*64 + tx*4 + j;
                v += bias[h*D + e];
                size_t oidx = ((size_t)(h*B + bb)*T + t)*D + e;
                switch (proj) {
                    case 0: g_q [oidx] = v; break;
                    case 1: g_k [oidx] = v * INV_SQRT_D; break;
                    case 2: g_v [oidx] = v; break;
                    case 3: g_og[oidx] = 1.f / (1.f + expf(-v)); break;
                    default:g_sk[oidx] = v; break;
                }
            }
        }
    }
}

// ---------------- K4a: score partials, split-K over e ------------------------
__global__ __launch_bounds__(256) void k4a()
{
    __shared__ float As[16*68];
    __shared__ float Bs[16*68];

    int hb = blockIdx.x;
    int kz = blockIdx.y;
    int tid = threadIdx.x;
    int tx = tid & 15;
    int ty = tid >> 4;

    const float* Qg = g_q + (size_t)hb*T*D + kz*64;
    const float* Kg = g_k + (size_t)hb*T*D + kz*64;

    u64 acc2[2][4];
    #pragma unroll
    for (int i = 0; i < 2; i++)
        #pragma unroll
        for (int j = 0; j < 4; j++) acc2[i][j] = 0ull;

    for (int ch = 0; ch < 4; ch++) {
        #pragma unroll
        for (int i = 0; i < 4; i++) {
            int e = tid + 256*i;
            int r = e >> 4, c = e & 15;
            As[c*68 + r] = Qg[r*D + ch*16 + c];
            Bs[c*68 + r] = Kg[r*D + ch*16 + c];
        }
        __syncthreads();
        #pragma unroll
        for (int kk = 0; kk < 16; kk++) {
            float4 a4 = *(const float4*)&As[kk*68 + ty*4];
            float4 b4 = *(const float4*)&Bs[kk*68 + tx*4];
            u64 ap[2] = {pack2(a4.x, a4.y), pack2(a4.z, a4.w)};
            u64 bb[4] = {bcast2(b4.x), bcast2(b4.y), bcast2(b4.z), bcast2(b4.w)};
            #pragma unroll
            for (int i = 0; i < 2; i++)
                #pragma unroll
                for (int j = 0; j < 4; j++) ffma2(acc2[i][j], ap[i], bb[j]);
        }
        __syncthreads();
    }

    float* out = g_wp + ((size_t)(hb*4 + kz))*T*T;
    #pragma unroll
    for (int ip = 0; ip < 2; ip++) {
        float2 p0 = unpack2(acc2[ip][0]);
        float2 p1 = unpack2(acc2[ip][1]);
        float2 p2 = unpack2(acc2[ip][2]);
        float2 p3 = unpack2(acc2[ip][3]);
        *(float4*)&out[(ty*4 + ip*2    )*T + tx*4] = make_float4(p0.x, p1.x, p2.x, p3.x);
        *(float4*)&out[(ty*4 + ip*2 + 1)*T + tx*4] = make_float4(p0.y, p1.y, p2.y, p3.y);
    }
}

// ---------------- K4b: combine + decay/mask/rowsum + O=W.V fused -------------
__global__ __launch_bounds__(256) void k4b()
{
    __shared__ float WsT[64*68];
    __shared__ float Vs [64*68];
    __shared__ float sc_s[64];
    __shared__ float ad_s[64];
    __shared__ float bd_s[64];

    int hb = blockIdx.x;
    int h = hb / B, b = hb % B;
    int eoff = blockIdx.y * 64;
    int tid = threadIdx.x;

    if (tid < 64) {
        ad_s[tid] = g_ad[tid*HB + hb];
        bd_s[tid] = g_bd[tid*HB + hb];
    }
    __syncthreads();

    const float* wp = g_wp + (size_t)hb*4*T*T;
    for (int i = tid; i < T*T; i += 256) {
        int t = i >> 6, s = i & 63;
        float p = wp[i] + wp[T*T + i] + wp[2*T*T + i] + wp[3*T*T + i];
        float w = (s <= t) ? expf(ad_s[s] + bd_s[t]) * p : 0.f;
        WsT[s*68 + t] = w;
    }
    const float* Vg = g_v + (size_t)hb*T*D;
    for (int i = tid; i < 64*64; i += 256) {
        int s = i >> 6, el = i & 63;
        Vs[s*68 + el] = Vg[s*D + eoff + el];
    }
    __syncthreads();

    if (tid < 64) {
        float r = 0.f;
        #pragma unroll 8
        for (int s = 0; s < 64; s++) r += WsT[s*68 + tid];
        sc_s[tid] = 1.f / fmaxf(fabsf(r), 1.f);
    }
    __syncthreads();

    int tx = tid & 15;
    int ty = tid >> 4;

    u64 acc2[2][4];
    #pragma unroll
    for (int i = 0; i < 2; i++)
        #pragma unroll
        for (int j = 0; j < 4; j++) acc2[i][j] = 0ull;

    #pragma unroll 4
    for (int s = 0; s < 64; s++) {
        float4 w4 = *(const float4*)&WsT[s*68 + ty*4];
        float4 v4 = *(const float4*)&Vs [s*68 + tx*4];
        u64 ap[2] = {pack2(w4.x, w4.y), pack2(w4.z, w4.w)};
        u64 bb[4] = {bcast2(v4.x), bcast2(v4.y), bcast2(v4.z), bcast2(v4.w)};
        #pragma unroll
        for (int i = 0; i < 2; i++)
            #pragma unroll
            for (int j = 0; j < 4; j++) ffma2(acc2[i][j], ap[i], bb[j]);
    }

    const float* OGg = g_og + (size_t)hb*T*D;
    const float* SKg = g_sk + (size_t)hb*T*D;
    #pragma unroll
    for (int ip = 0; ip < 2; ip++) {
        #pragma unroll
        for (int half = 0; half < 2; half++) {
            int t = ty*4 + ip*2 + half;
            float scv = sc_s[t];
            float4 og4 = *(const float4*)&OGg[t*D + eoff + tx*4];
            float4 sk4 = *(const float4*)&SKg[t*D + eoff + tx*4];
            float av[4];
            #pragma unroll
            for (int j = 0; j < 4; j++) {
                float2 pr = unpack2(acc2[ip][j]);
                av[j] = half ? pr.y : pr.x;
            }
            float4 hv;
            hv.x = og4.x * av[0] * scv + sk4.x;
            hv.y = og4.y * av[1] * scv + sk4.y;
            hv.z = og4.z * av[2] * scv + sk4.z;
            hv.w = og4.w * av[3] * scv + sk4.w;
            *(float4*)&g_h[((size_t)(t*NH + h)*B + b)*D + eoff + tx*4] = hv;
        }
    }
}

// ---------------- K5a: BN2 + re-layout ---------------------------------------
__global__ __launch_bounds__(256) void k5a(const float* __restrict__ bn2_s,
                                           const float* __restrict__ bn2_b)
{
    int t = blockIdx.x;
    int tid = threadIdx.x;
    __shared__ float hs[32*257];

    for (int i = tid; i < 32*256; i += 256) {
        int p = i >> 8, d = i & 255;
        hs[p*257 + d] = g_h[(size_t)t*NH*B*D + p*256 + d];
    }
    __syncthreads();

    int d = tid;
    float s = 0.f, s2 = 0.f;
    #pragma unroll
    for (int p = 0; p < 32; p++) { float v = hs[p*257 + d]; s += v; s2 += v*v; }
    float mu  = s * (1.f/32);
    float var = s2 * (1.f/32) - mu*mu;
    float inv = rsqrtf(var + EPS);
    float sc = bn2_s[d]*inv, ofs = bn2_b[d];
    #pragma unroll
    for (int p = 0; p < 32; p++) {
        int hh = p >> 3, bb = p & 7;
        g_hn[(size_t)(t*B + bb)*(NH*D) + hh*D + d] = (hs[p*257 + d] - mu)*sc + ofs;
    }
}

// ---------------- K5b: poll GEMM, K-split 4, FFMA2 ---------------------------
__global__ __launch_bounds__(256) void k5b(const float* __restrict__ Wpoll)
{
    int tm = blockIdx.x;
    int tn = blockIdx.y;
    int kz = blockIdx.z;

    __shared__ float As[32*68];
    __shared__ float Bs[32*68];

    int tid = threadIdx.x;
    int tx = tid & 15;
    int ty = tid >> 4;

    u64 acc2[2][4];
    #pragma unroll
    for (int i = 0; i < 2; i++)
        #pragma unroll
        for (int j = 0; j < 4; j++) acc2[i][j] = 0ull;

    for (int kt = 0; kt < 8; kt++) {
        int k0 = kz*256 + kt*32;
        #pragma unroll
        for (int i = 0; i < 8; i++) {
            int e = tid + 256*i;
            int r = e >> 5, c = e & 31;
            As[c*68 + r] = g_hn[(size_t)(tm*64 + r)*(NH*D) + k0 + c];
        }
        #pragma unroll
        for (int i = 0; i < 8; i++) {
            int e = tid + 256*i;
            int kr = e >> 6, cc = e & 63;
            Bs[kr*68 + cc] = Wpoll[(size_t)(k0 + kr)*D + tn*64 + cc];
        }
        __syncthreads();
        #pragma unroll
        for (int kk = 0; kk < 32; kk++) {
            float4 a4 = *(const float4*)&As[kk*68 + ty*4];
            float4 b4 = *(const float4*)&Bs[kk*68 + tx*4];
            u64 ap[2] = {pack2(a4.x, a4.y), pack2(a4.z, a4.w)};
            u64 bb[4] = {bcast2(b4.x), bcast2(b4.y), bcast2(b4.z), bcast2(b4.w)};
            #pragma unroll
            for (int i = 0; i < 2; i++)
                #pragma unroll
                for (int j = 0; j < 4; j++) ffma2(acc2[i][j], ap[i], bb[j]);
        }
        __syncthreads();
    }

    #pragma unroll
    for (int ip = 0; ip < 2; ip++) {
        float2 p0 = unpack2(acc2[ip][0]);
        float2 p1 = unpack2(acc2[ip][1]);
        float2 p2 = unpack2(acc2[ip][2]);
        float2 p3 = unpack2(acc2[ip][3]);
        int row0 = tm*64 + ty*4 + ip*2;
        *(float4*)&g_pp[(size_t)kz*T*B*D + (size_t)row0*D + tn*64 + tx*4] =
            make_float4(p0.x, p1.x, p2.x, p3.x);
        *(float4*)&g_pp[(size_t)kz*T*B*D + (size_t)(row0+1)*D + tn*64 + tx*4] =
            make_float4(p0.y, p1.y, p2.y, p3.y);
    }
}

// ---------------- K5c: combine partials + trig gate + down + residual --------
__global__ __launch_bounds__(256) void k5c(
    const float* __restrict__ x,
    const float* __restrict__ bpoll,
    const float* __restrict__ Wdown, const float* __restrict__ bdown,
    float* __restrict__ out)
{
    int t = blockIdx.x;
    int tid = threadIdx.x;
    __shared__ float ps[B*D];

    for (int i = tid; i < B*D; i += 256) {
        int bb = i >> 8, e = i & 255;
        size_t row = (size_t)(t*B + bb)*D + e;
        float pv = g_pp[row] + g_pp[(size_t)T*B*D + row]
                 + g_pp[(size_t)2*T*B*D + row] + g_pp[(size_t)3*T*B*D + row]
                 + bpoll[e];
        ps[bb*D + e] = pv * g_trig[row];
    }
    __syncthreads();

    int j = tid & 127;
    int bg = tid >> 7;
    float acc[4] = {0.f, 0.f, 0.f, 0.f};
    for (int e = 0; e < D; e++) {
        float w = Wdown[e*H + j];
        #pragma unroll
        for (int q = 0; q < 4; q++) acc[q] = fmaf(ps[(bg*4 + q)*D + e], w, acc[q]);
    }
    #pragma unroll
    for (int q = 0; q < 4; q++) {
        int bb = bg*4 + q;
        out[(t*B + bb)*H + j] = acc[q] + bdown[j] + x[(t*B + bb)*H + j];
    }
}

// ---------------- launch -----------------------------------------------------
extern "C" void kernel_launch(void* const* d_in, const int* in_sizes, int n_in,
                              void* d_out, int out_size)
{
    const float* x      = (const float*)d_in[0];
    const float* Wq     = (const float*)d_in[1];
    const float* bq     = (const float*)d_in[2];
    const float* Wk     = (const float*)d_in[3];
    const float* bk     = (const float*)d_in[4];
    const float* Wv     = (const float*)d_in[5];
    const float* bv     = (const float*)d_in[6];
    const float* convk  = (const float*)d_in[7];
    const float* convb  = (const float*)d_in[8];
    const float* Wi     = (const float*)d_in[9];
    const float* bi     = (const float*)d_in[10];
    const float* Wf     = (const float*)d_in[11];
    const float* bf     = (const float*)d_in[12];
    const float* Wo     = (const float*)d_in[13];
    const float* bo     = (const float*)d_in[14];
    const float* Wsk    = (const float*)d_in[15];
    const float* bsk    = (const float*)d_in[16];
    const float* bn1_s  = (const float*)d_in[17];
    const float* bn1_b  = (const float*)d_in[18];
    const float* bn2_s  = (const float*)d_in[19];
    const float* bn2_b  = (const float*)d_in[20];
    const float* Wup1   = (const float*)d_in[21];
    const float* bup1   = (const float*)d_in[22];
    const float* Wup2   = (const float*)d_in[23];
    const float* bup2   = (const float*)d_in[24];
    const float* Wpoll  = (const float*)d_in[25];
    const float* bpoll  = (const float*)d_in[26];
    const float* Wdown  = (const float*)d_in[27];
    const float* bdown  = (const float*)d_in[28];
    float* out = (float*)d_out;

    k1a<<<T, 128>>>(x, bn1_s, bn1_b);
    k1b<<<dim3(8, 8), 256>>>(Wup1, bup1, Wup2, bup2);
    k1c<<<T, 256>>>(convk, convb, Wi, bi, Wf, bf);
    k2_scan<<<1, 256>>>();
    k3_gemm<<<dim3(16, 20), 256>>>(Wq, bq, Wk, bk, Wv, bv, Wo, bo, Wsk, bsk);
    k4a<<<dim3(HB, 4), 256>>>();
    k4b<<<dim3(HB, 4), 256>>>();
    k5a<<<T, 256>>>(bn2_s, bn2_b);
    k5b<<<dim3(8, 4, 4), 256>>>(Wpoll);
    k5c<<<T, 256>>>(x, bpoll, Wdown, bdown, out);
}

// round 9
// speedup vs baseline: 1.8843x; 1.0197x over previous
#include <cuda_runtime.h>
#include <cuda_bf16.h>
#include <cstdint>

// Dims
#define T 64
#define B 8
#define H 128
#define NH 4
#define D 256
#define HB (NH*B)          // 32
#define EPS 1e-5f
#define INV_SQRT_D 0.0625f

typedef unsigned long long u64;

// ---- packed f32x2 helpers (SASS FFMA2) --------------------------------------
__device__ __forceinline__ u64 pack2(float x, float y) {
    u64 r; asm("mov.b64 %0, {%1,%2};" : "=l"(r) : "f"(x), "f"(y)); return r;
}
__device__ __forceinline__ u64 bcast2(float x) {
    u64 r; asm("mov.b64 %0, {%1,%1};" : "=l"(r) : "f"(x)); return r;
}
__device__ __forceinline__ void ffma2(u64& d, u64 a, u64 b) {
    asm("fma.rn.f32x2 %0, %1, %2, %3;" : "=l"(d) : "l"(a), "l"(b), "l"(d));
}
__device__ __forceinline__ float2 unpack2(u64 v) {
    float x, y; asm("mov.b64 {%0,%1}, %2;" : "=f"(x), "=f"(y) : "l"(v));
    return make_float2(x, y);
}

// ---------------- scratch (device globals; no allocation) ----------------
__device__ float g_xin [T*B*D];
__device__ float g_trig[T*B*D];
__device__ float g_qk  [T*NH*B*D];
__device__ float g_ipre[T*HB];
__device__ float g_fpre[T*HB];
__device__ float g_ad  [T*HB];
__device__ float g_bd  [T*HB];
__device__ float g_q [NH*B*T*D];     // [hb][t][e]
__device__ float g_k [NH*B*T*D];
__device__ float g_v [NH*B*T*D];
__device__ float g_og[NH*B*T*D];
__device__ float g_sk[NH*B*T*D];
__device__ float g_h [T*NH*B*D];     // [t][h][b][d]
__device__ float g_hn[T*B*NH*D];     // BN2'd, [(t*B+b)][h*D+d]
__device__ float g_pp[4*T*B*D];      // poll partials [kz][(t*B+b)][e]

// ---------------- K1b: BN1 (inline) + up-proj GEMM [512,128]x[128,512] -------
// cols 0..255 -> g_xin (+bup1), cols 256..511 -> silu -> g_trig (+bup2)
__global__ __launch_bounds__(256) void k1b(const float* __restrict__ x,
                                           const float* __restrict__ bn1_s,
                                           const float* __restrict__ bn1_b,
                                           const float* __restrict__ Wup1,
                                           const float* __restrict__ bup1,
                                           const float* __restrict__ Wup2,
                                           const float* __restrict__ bup2)
{
    int tm = blockIdx.x;   // 0..7
    int tn = blockIdx.y;   // 0..7

    __shared__ float As[32*68];  // k-major As[c*68 + r]
    __shared__ float Bs[32*68];

    int tid = threadIdx.x;
    int tx = tid & 15;
    int ty = tid >> 4;

    u64 acc2[2][4];
    #pragma unroll
    for (int i = 0; i < 2; i++)
        #pragma unroll
        for (int j = 0; j < 4; j++) acc2[i][j] = 0ull;

    for (int kt = 0; kt < 4; kt++) {
        // load raw x chunk: rows tm*64.., cols kt*32..
        #pragma unroll
        for (int i = 0; i < 8; i++) {
            int e = tid + 256*i;
            int r = e >> 5, c = e & 31;
            As[c*68 + r] = x[(tm*64 + r)*H + kt*32 + c];
        }
        #pragma unroll
        for (int i = 0; i < 8; i++) {
            int e = tid + 256*i;
            int kr = e >> 6, cc = e & 63;
            int jrow = kt*32 + kr;
            int col = tn*64 + cc;
            float w = (col < 256) ? Wup1[jrow*D + col] : Wup2[jrow*D + col - 256];
            Bs[kr*68 + cc] = w;
        }
        __syncthreads();

        // BN1 inline: thread handles (t_local, c); stats over the 8 batch rows
        {
            int tl = tid >> 5;          // 0..7 local t
            int c  = tid & 31;
            float* base = &As[c*68 + tl*8];
            float s = 0.f, s2 = 0.f;
            #pragma unroll
            for (int bb = 0; bb < 8; bb++) { float v = base[bb]; s += v; s2 += v*v; }
            float mu  = s * 0.125f;
            float var = s2 * 0.125f - mu*mu;
            float inv = rsqrtf(var + EPS);
            int j = kt*32 + c;
            float sc = bn1_s[j]*inv, ofs = bn1_b[j];
            #pragma unroll
            for (int bb = 0; bb < 8; bb++) base[bb] = (base[bb] - mu)*sc + ofs;
        }
        __syncthreads();

        #pragma unroll
        for (int kk = 0; kk < 32; kk++) {
            float4 a4 = *(const float4*)&As[kk*68 + ty*4];
            float4 b4 = *(const float4*)&Bs[kk*68 + tx*4];
            u64 ap[2] = {pack2(a4.x, a4.y), pack2(a4.z, a4.w)};
            u64 bb[4] = {bcast2(b4.x), bcast2(b4.y), bcast2(b4.z), bcast2(b4.w)};
            #pragma unroll
            for (int i = 0; i < 2; i++)
                #pragma unroll
                for (int j = 0; j < 4; j++) ffma2(acc2[i][j], ap[i], bb[j]);
        }
        __syncthreads();
    }

    bool istrig = (tn >= 4);
    #pragma unroll
    for (int ip = 0; ip < 2; ip++) {
        #pragma unroll
        for (int half = 0; half < 2; half++) {
            int row = tm*64 + ty*4 + ip*2 + half;
            int col = tn*64 + tx*4;
            float rv[4];
            #pragma unroll
            for (int j = 0; j < 4; j++) {
                float2 p = unpack2(acc2[ip][j]);
                rv[j] = half ? p.y : p.x;
            }
            if (!istrig) {
                float4 o;
                o.x = rv[0] + bup1[col+0];
                o.y = rv[1] + bup1[col+1];
                o.z = rv[2] + bup1[col+2];
                o.w = rv[3] + bup1[col+3];
                *(float4*)&g_xin[(size_t)row*D + col] = o;
            } else {
                int c2 = col - 256;
                float4 o; float tv;
                tv = rv[0] + bup2[c2+0]; o.x = tv / (1.f + expf(-tv));
                tv = rv[1] + bup2[c2+1]; o.y = tv / (1.f + expf(-tv));
                tv = rv[2] + bup2[c2+2]; o.z = tv / (1.f + expf(-tv));
                tv = rv[3] + bup2[c2+3]; o.w = tv / (1.f + expf(-tv));
                *(float4*)&g_trig[(size_t)row*D + c2] = o;
            }
        }
    }
}

// ---------------- K1c: conv/qk + gate pre-acts -------------------------------
__global__ __launch_bounds__(256) void k1c(const float* __restrict__ convk,
                                           const float* __restrict__ convb,
                                           const float* __restrict__ Wi,
                                           const float* __restrict__ bi,
                                           const float* __restrict__ Wf,
                                           const float* __restrict__ bf)
{
    int t = blockIdx.x;
    int tid = threadIdx.x;
    __shared__ float xins[B*D];

    for (int i = tid; i < B*D; i += 256) xins[i] = g_xin[(size_t)t*B*D + i];
    __syncthreads();

    for (int idx = tid; idx < NH*B*D; idx += 256) {
        int hh = idx / (B*D);
        int rem = idx % (B*D);
        int bb = rem / D, dd = rem % D;
        float acc = convb[hh];
        #pragma unroll
        for (int w = 0; w < 4; w++) {
            int dj = dd - 1 + w;
            if (dj >= 0 && dj < D) acc = fmaf(xins[bb*D + dj], convk[w*NH + hh], acc);
        }
        g_qk[((t*NH + hh)*B + bb)*D + dd] = acc / (1.f + expf(-acc));
    }

    {
        int g = tid >> 2;
        int r = tid & 3;
        int which = g >> 5;
        int p = g & 31;
        int hh = p >> 3, bb = p & 7;
        const float* W = which ? (Wf + hh*D) : (Wi + hh*D);
        const float* xb = xins + bb*D;
        float acc = 0.f;
        for (int u = 0; u < 64; u++) {
            int dd = r + 4*u;
            acc = fmaf(xb[dd], W[dd], acc);
        }
        acc += __shfl_xor_sync(0xffffffffu, acc, 1);
        acc += __shfl_xor_sync(0xffffffffu, acc, 2);
        if (r == 0) {
            if (which) g_fpre[t*HB + p] = acc + bf[hh];
            else       g_ipre[t*HB + p] = acc + bi[hh];
        }
    }
}

// ---------------- K2: warp-parallel gate scan --------------------------------
// cf: plain cumsum.  m: max-plus affine maps x->max(x+f, i); composition
// (F1,I1) then (F2,I2) = (F1+F2, max(I1+F2, I2)).  Warp w handles p=w,
// lane l holds t=2l,2l+1; Hillis-Steele shfl scan.
__global__ __launch_bounds__(1024) void k2_scan()
{
    __shared__ float si[T*33];   // [t*33 + p] padded
    __shared__ float sf[T*33];
    int tid = threadIdx.x;

    for (int i = tid; i < T*HB; i += 1024) {
        int t = i >> 5, p = i & 31;
        si[t*33 + p] = g_ipre[i];
        sf[t*33 + p] = g_fpre[i];
    }
    __syncthreads();

    int p = tid >> 5;
    int l = tid & 31;
    int t0 = 2*l, t1 = 2*l + 1;
    float f0 = sf[t0*33 + p], f1 = sf[t1*33 + p];
    float i0 = si[t0*33 + p], i1 = si[t1*33 + p];

    // cumsum of f
    float ps = f0 + f1;
    float s = ps;
    #pragma unroll
    for (int d = 1; d < 32; d <<= 1) {
        float o = __shfl_up_sync(0xffffffffu, s, d);
        if (l >= d) s += o;
    }
    float excl = s - ps;
    float cf0 = excl + f0;
    float cf1 = excl + ps;

    // max-plus scan
    float F = f0 + f1;
    float I = fmaxf(i0 + f1, i1);
    #pragma unroll
    for (int d = 1; d < 32; d <<= 1) {
        float Fo = __shfl_up_sync(0xffffffffu, F, d);
        float Io = __shfl_up_sync(0xffffffffu, I, d);
        if (l >= d) {
            I = fmaxf(Io + F, I);   // uses current-segment F before update
            F = Fo + F;
        }
    }
    float m1 = fmaxf(F, I);                      // m at t1 (applied to m0=0)
    float Fe = __shfl_up_sync(0xffffffffu, F, 1);
    float Ie = __shfl_up_sync(0xffffffffu, I, 1);
    if (l == 0) { Fe = 0.f; Ie = -3.0e38f; }
    float m0v = fmaxf(Fe + f0, fmaxf(Ie + f0, i0));  // m at t0

    g_ad[t0*HB + p] = i0 - cf0;
    g_ad[t1*HB + p] = i1 - cf1;
    g_bd[t0*HB + p] = cf0 - m0v;
    g_bd[t1*HB + p] = cf1 - m1;
}

// ---------------- K3: batched projection GEMMs (128x64, FFMA2) ---------------
__global__ __launch_bounds__(256) void k3_gemm(
    const float* __restrict__ Wq, const float* __restrict__ bq,
    const float* __restrict__ Wk, const float* __restrict__ bk,
    const float* __restrict__ Wv, const float* __restrict__ bv,
    const float* __restrict__ Wo, const float* __restrict__ bo,
    const float* __restrict__ Wsk,const float* __restrict__ bsk)
{
    int inst = blockIdx.y;           // 0..19
    int proj = inst / NH;
    int h    = inst % NH;
    int tm = blockIdx.x & 3;
    int tn = blockIdx.x >> 2;

    const float* W; const float* bias; int src;
    switch (proj) {
        case 0: W = Wq;  bias = bq;  src = 0; break;
        case 1: W = Wk;  bias = bk;  src = 0; break;
        case 2: W = Wv;  bias = bv;  src = 1; break;
        case 3: W = Wo;  bias = bo;  src = 1; break;
        default:W = Wsk; bias = bsk; src = 0; break;
    }

    __shared__ float As[32*132];
    __shared__ float Bs[32*68];

    int tid = threadIdx.x;
    int tx = tid & 15;
    int ty = tid >> 4;

    u64 acc2[4][4];
    #pragma unroll
    for (int i = 0; i < 4; i++)
        #pragma unroll
        for (int j = 0; j < 4; j++) acc2[i][j] = 0ull;

    const float* Wb = W + (size_t)h*D*D;

    for (int kt = 0; kt < 8; kt++) {
        #pragma unroll
        for (int i = 0; i < 16; i++) {
            int e = tid + 256*i;
            int r = e >> 5, c = e & 31;
            int gr = tm*128 + r;
            int t = gr >> 3, bb = gr & 7;
            int dcol = kt*32 + c;
            float av = (src == 0) ? g_qk[((t*NH + h)*B + bb)*D + dcol]
                                  : g_xin[(t*B + bb)*D + dcol];
            As[c*132 + r] = av;
        }
        #pragma unroll
        for (int i = 0; i < 8; i++) {
            int e = tid + 256*i;
            int kr = e >> 6, cc = e & 63;
            Bs[kr*68 + cc] = Wb[(kt*32 + kr)*D + tn*64 + cc];
        }
        __syncthreads();
        #pragma unroll
        for (int kk = 0; kk < 32; kk++) {
            float4 a0 = *(const float4*)&As[kk*132 + ty*8];
            float4 a1 = *(const float4*)&As[kk*132 + ty*8 + 4];
            float4 b4 = *(const float4*)&Bs[kk*68 + tx*4];
            u64 ap[4] = {pack2(a0.x,a0.y), pack2(a0.z,a0.w),
                         pack2(a1.x,a1.y), pack2(a1.z,a1.w)};
            u64 bb2[4] = {bcast2(b4.x), bcast2(b4.y), bcast2(b4.z), bcast2(b4.w)};
            #pragma unroll
            for (int i = 0; i < 4; i++)
                #pragma unroll
                for (int j = 0; j < 4; j++) ffma2(acc2[i][j], ap[i], bb2[j]);
        }
        __syncthreads();
    }

    #pragma unroll
    for (int ip = 0; ip < 4; ip++) {
        #pragma unroll
        for (int half = 0; half < 2; half++) {
            int gr = tm*128 + ty*8 + ip*2 + half;
            int t = gr >> 3, bb = gr & 7;
            #pragma unroll
            for (int j = 0; j < 4; j++) {
                float2 pr = unpack2(acc2[ip][j]);
                float v = (half ? pr.y : pr.x);
                int e = tn*64 + tx*4 + j;
                v += bias[h*D + e];
                size_t oidx = ((size_t)(h*B + bb)*T + t)*D + e;
                switch (proj) {
                    case 0: g_q [oidx] = v; break;
                    case 1: g_k [oidx] = v * INV_SQRT_D; break;
                    case 2: g_v [oidx] = v; break;
                    case 3: g_og[oidx] = 1.f / (1.f + expf(-v)); break;
                    default:g_sk[oidx] = v; break;
                }
            }
        }
    }
}

// ---------------- K4: fused S=QK^T + decay/mask/rowsum + O=W.V ---------------
// grid (HB, 4): block recomputes full S (in regs), outputs e-slice [y*64..)
__global__ __launch_bounds__(256) void k4()
{
    __shared__ float WsT[64*68];   // phase2: Q-chunk [c<32][r<64]; phase3+: W^T
    __shared__ float Vs [64*68];   // phase2: K-chunk;              phase3+: V
    __shared__ float ad_s[64];
    __shared__ float bd_s[64];
    __shared__ float sc_s[64];

    int hb = blockIdx.x;
    int h = hb >> 3, b = hb & 7;
    int eoff = blockIdx.y * 64;
    int tid = threadIdx.x;
    int tx = tid & 15;
    int ty = tid >> 4;

    if (tid < 64) {
        ad_s[tid] = g_ad[tid*HB + hb];
        bd_s[tid] = g_bd[tid*HB + hb];
    }

    const float* Qg = g_q + (size_t)hb*T*D;
    const float* Kg = g_k + (size_t)hb*T*D;

    u64 acc2[2][4];
    #pragma unroll
    for (int i = 0; i < 2; i++)
        #pragma unroll
        for (int j = 0; j < 4; j++) acc2[i][j] = 0ull;

    // phase 2: S = Q.K^T over all 256 e in 8 chunks of 32
    for (int ch = 0; ch < 8; ch++) {
        #pragma unroll
        for (int i = 0; i < 8; i++) {
            int e = tid + 256*i;
            int r = e >> 5, c = e & 31;
            WsT[c*68 + r] = Qg[r*D + ch*32 + c];
            Vs [c*68 + r] = Kg[r*D + ch*32 + c];
        }
        __syncthreads();
        #pragma unroll
        for (int kk = 0; kk < 32; kk++) {
            float4 a4 = *(const float4*)&WsT[kk*68 + ty*4];
            float4 b4 = *(const float4*)&Vs [kk*68 + tx*4];
            u64 ap[2] = {pack2(a4.x, a4.y), pack2(a4.z, a4.w)};
            u64 bb[4] = {bcast2(b4.x), bcast2(b4.y), bcast2(b4.z), bcast2(b4.w)};
            #pragma unroll
            for (int i = 0; i < 2; i++)
                #pragma unroll
                for (int j = 0; j < 4; j++) ffma2(acc2[i][j], ap[i], bb[j]);
        }
        __syncthreads();
    }

    // phase 3: decay/mask, store W transposed; load V
    #pragma unroll
    for (int ip = 0; ip < 2; ip++) {
        #pragma unroll
        for (int half = 0; half < 2; half++) {
            int t = ty*4 + ip*2 + half;
            float bdv = bd_s[t];
            #pragma unroll
            for (int j = 0; j < 4; j++) {
                int s = tx*4 + j;
                float2 pr = unpack2(acc2[ip][j]);
                float val = half ? pr.y : pr.x;
                float w = (s <= t) ? expf(ad_s[s] + bdv) * val : 0.f;
                WsT[s*68 + t] = w;
            }
        }
    }
    const float* Vg = g_v + (size_t)hb*T*D;
    #pragma unroll
    for (int i = 0; i < 16; i++) {
        int e2 = tid + 256*i;
        int s = e2 >> 6, el = e2 & 63;
        Vs[s*68 + el] = Vg[s*D + eoff + el];
    }
    __syncthreads();

    // phase 4: rowsum -> scaler
    if (tid < 64) {
        float r = 0.f;
        #pragma unroll 8
        for (int s = 0; s < 64; s++) r += WsT[s*68 + tid];
        sc_s[tid] = 1.f / fmaxf(fabsf(r), 1.f);
    }
    __syncthreads();

    // phase 5: O = W.V
    u64 oacc[2][4];
    #pragma unroll
    for (int i = 0; i < 2; i++)
        #pragma unroll
        for (int j = 0; j < 4; j++) oacc[i][j] = 0ull;

    #pragma unroll 4
    for (int s = 0; s < 64; s++) {
        float4 w4 = *(const float4*)&WsT[s*68 + ty*4];
        float4 v4 = *(const float4*)&Vs [s*68 + tx*4];
        u64 ap[2] = {pack2(w4.x, w4.y), pack2(w4.z, w4.w)};
        u64 bb[4] = {bcast2(v4.x), bcast2(v4.y), bcast2(v4.z), bcast2(v4.w)};
        #pragma unroll
        for (int i = 0; i < 2; i++)
            #pragma unroll
            for (int j = 0; j < 4; j++) ffma2(oacc[i][j], ap[i], bb[j]);
    }

    const float* OGg = g_og + (size_t)hb*T*D;
    const float* SKg = g_sk + (size_t)hb*T*D;
    #pragma unroll
    for (int ip = 0; ip < 2; ip++) {
        #pragma unroll
        for (int half = 0; half < 2; half++) {
            int t = ty*4 + ip*2 + half;
            float scv = sc_s[t];
            float4 og4 = *(const float4*)&OGg[t*D + eoff + tx*4];
            float4 sk4 = *(const float4*)&SKg[t*D + eoff + tx*4];
            float av[4];
            #pragma unroll
            for (int j = 0; j < 4; j++) {
                float2 pr = unpack2(oacc[ip][j]);
                av[j] = half ? pr.y : pr.x;
            }
            float4 hv;
            hv.x = og4.x * av[0] * scv + sk4.x;
            hv.y = og4.y * av[1] * scv + sk4.y;
            hv.z = og4.z * av[2] * scv + sk4.z;
            hv.w = og4.w * av[3] * scv + sk4.w;
            *(float4*)&g_h[((size_t)(t*NH + h)*B + b)*D + eoff + tx*4] = hv;
        }
    }
}

// ---------------- K5a: BN2 + re-layout ---------------------------------------
__global__ __launch_bounds__(256) void k5a(const float* __restrict__ bn2_s,
                                           const float* __restrict__ bn2_b)
{
    int t = blockIdx.x;
    int tid = threadIdx.x;
    __shared__ float hs[32*257];

    for (int i = tid; i < 32*256; i += 256) {
        int p = i >> 8, d = i & 255;
        hs[p*257 + d] = g_h[(size_t)t*NH*B*D + p*256 + d];
    }
    __syncthreads();

    int d = tid;
    float s = 0.f, s2 = 0.f;
    #pragma unroll
    for (int p = 0; p < 32; p++) { float v = hs[p*257 + d]; s += v; s2 += v*v; }
    float mu  = s * (1.f/32);
    float var = s2 * (1.f/32) - mu*mu;
    float inv = rsqrtf(var + EPS);
    float sc = bn2_s[d]*inv, ofs = bn2_b[d];
    #pragma unroll
    for (int p = 0; p < 32; p++) {
        int hh = p >> 3, bb = p & 7;
        g_hn[(size_t)(t*B + bb)*(NH*D) + hh*D + d] = (hs[p*257 + d] - mu)*sc + ofs;
    }
}

// ---------------- K5b: poll GEMM, K-split 4, FFMA2 ---------------------------
__global__ __launch_bounds__(256) void k5b(const float* __restrict__ Wpoll)
{
    int tm = blockIdx.x;
    int tn = blockIdx.y;
    int kz = blockIdx.z;

    __shared__ float As[32*68];
    __shared__ float Bs[32*68];

    int tid = threadIdx.x;
    int tx = tid & 15;
    int ty = tid >> 4;

    u64 acc2[2][4];
    #pragma unroll
    for (int i = 0; i < 2; i++)
        #pragma unroll
        for (int j = 0; j < 4; j++) acc2[i][j] = 0ull;

    for (int kt = 0; kt < 8; kt++) {
        int k0 = kz*256 + kt*32;
        #pragma unroll
        for (int i = 0; i < 8; i++) {
            int e = tid + 256*i;
            int r = e >> 5, c = e & 31;
            As[c*68 + r] = g_hn[(size_t)(tm*64 + r)*(NH*D) + k0 + c];
        }
        #pragma unroll
        for (int i = 0; i < 8; i++) {
            int e = tid + 256*i;
            int kr = e >> 6, cc = e & 63;
            Bs[kr*68 + cc] = Wpoll[(size_t)(k0 + kr)*D + tn*64 + cc];
        }
        __syncthreads();
        #pragma unroll
        for (int kk = 0; kk < 32; kk++) {
            float4 a4 = *(const float4*)&As[kk*68 + ty*4];
            float4 b4 = *(const float4*)&Bs[kk*68 + tx*4];
            u64 ap[2] = {pack2(a4.x, a4.y), pack2(a4.z, a4.w)};
            u64 bb[4] = {bcast2(b4.x), bcast2(b4.y), bcast2(b4.z), bcast2(b4.w)};
            #pragma unroll
            for (int i = 0; i < 2; i++)
                #pragma unroll
                for (int j = 0; j < 4; j++) ffma2(acc2[i][j], ap[i], bb[j]);
        }
        __syncthreads();
    }

    #pragma unroll
    for (int ip = 0; ip < 2; ip++) {
        float2 p0 = unpack2(acc2[ip][0]);
        float2 p1 = unpack2(acc2[ip][1]);
        float2 p2 = unpack2(acc2[ip][2]);
        float2 p3 = unpack2(acc2[ip][3]);
        int row0 = tm*64 + ty*4 + ip*2;
        *(float4*)&g_pp[(size_t)kz*T*B*D + (size_t)row0*D + tn*64 + tx*4] =
            make_float4(p0.x, p1.x, p2.x, p3.x);
        *(float4*)&g_pp[(size_t)kz*T*B*D + (size_t)(row0+1)*D + tn*64 + tx*4] =
            make_float4(p0.y, p1.y, p2.y, p3.y);
    }
}

// ---------------- K5c: combine partials + trig gate + down + residual --------
__global__ __launch_bounds__(256) void k5c(
    const float* __restrict__ x,
    const float* __restrict__ bpoll,
    const float* __restrict__ Wdown, const float* __restrict__ bdown,
    float* __restrict__ out)
{
    int t = blockIdx.x;
    int tid = threadIdx.x;
    __shared__ float ps[B*D];

    for (int i = tid; i < B*D; i += 256) {
        int bb = i >> 8, e = i & 255;
        size_t row = (size_t)(t*B + bb)*D + e;
        float pv = g_pp[row] + g_pp[(size_t)T*B*D + row]
                 + g_pp[(size_t)2*T*B*D + row] + g_pp[(size_t)3*T*B*D + row]
                 + bpoll[e];
        ps[bb*D + e] = pv * g_trig[row];
    }
    __syncthreads();

    int j = tid & 127;
    int bg = tid >> 7;
    float acc[4] = {0.f, 0.f, 0.f, 0.f};
    for (int e = 0; e < D; e++) {
        float w = Wdown[e*H + j];
        #pragma unroll
        for (int q = 0; q < 4; q++) acc[q] = fmaf(ps[(bg*4 + q)*D + e], w, acc[q]);
    }
    #pragma unroll
    for (int q = 0; q < 4; q++) {
        int bb = bg*4 + q;
        out[(t*B + bb)*H + j] = acc[q] + bdown[j] + x[(t*B + bb)*H + j];
    }
}

// ---------------- launch -----------------------------------------------------
extern "C" void kernel_launch(void* const* d_in, const int* in_sizes, int n_in,
                              void* d_out, int out_size)
{
    const float* x      = (const float*)d_in[0];
    const float* Wq     = (const float*)d_in[1];
    const float* bq     = (const float*)d_in[2];
    const float* Wk     = (const float*)d_in[3];
    const float* bk     = (const float*)d_in[4];
    const float* Wv     = (const float*)d_in[5];
    const float* bv     = (const float*)d_in[6];
    const float* convk  = (const float*)d_in[7];
    const float* convb  = (const float*)d_in[8];
    const float* Wi     = (const float*)d_in[9];
    const float* bi     = (const float*)d_in[10];
    const float* Wf     = (const float*)d_in[11];
    const float* bf     = (const float*)d_in[12];
    const float* Wo     = (const float*)d_in[13];
    const float* bo     = (const float*)d_in[14];
    const float* Wsk    = (const float*)d_in[15];
    const float* bsk    = (const float*)d_in[16];
    const float* bn1_s  = (const float*)d_in[17];
    const float* bn1_b  = (const float*)d_in[18];
    const float* bn2_s  = (const float*)d_in[19];
    const float* bn2_b  = (const float*)d_in[20];
    const float* Wup1   = (const float*)d_in[21];
    const float* bup1   = (const float*)d_in[22];
    const float* Wup2   = (const float*)d_in[23];
    const float* bup2   = (const float*)d_in[24];
    const float* Wpoll  = (const float*)d_in[25];
    const float* bpoll  = (const float*)d_in[26];
    const float* Wdown  = (const float*)d_in[27];
    const float* bdown  = (const float*)d_in[28];
    float* out = (float*)d_out;

    k1b<<<dim3(8, 8), 256>>>(x, bn1_s, bn1_b, Wup1, bup1, Wup2, bup2);
    k1c<<<T, 256>>>(convk, convb, Wi, bi, Wf, bf);
    k2_scan<<<1, 1024>>>();
    k3_gemm<<<dim3(16, 20), 256>>>(Wq, bq, Wk, bk, Wv, bv, Wo, bo, Wsk, bsk);
    k4<<<dim3(HB, 4), 256>>>();
    k5a<<<T, 256>>>(bn2_s, bn2_b);
    k5b<<<dim3(8, 4, 4), 256>>>(Wpoll);
    k5c<<<T, 256>>>(x, bpoll, Wdown, bdown, out);
}

// round 11
// speedup vs baseline: 1.9338x; 1.0263x over previous
#include <cuda_runtime.h>
#include <cuda_bf16.h>
#include <cstdint>

// Dims
#define T 64
#define B 8
#define H 128
#define NH 4
#define D 256
#define HB (NH*B)          // 32
#define EPS 1e-5f
#define INV_SQRT_D 0.0625f

typedef unsigned long long u64;

// ---- packed f32x2 helpers (SASS FFMA2) --------------------------------------
__device__ __forceinline__ u64 bcast2(float x) {
    u64 r; asm("mov.b64 %0, {%1,%1};" : "=l"(r) : "f"(x)); return r;
}
__device__ __forceinline__ void ffma2(u64& d, u64 a, u64 b) {
    asm("fma.rn.f32x2 %0, %1, %2, %3;" : "=l"(d) : "l"(a), "l"(b), "l"(d));
}
__device__ __forceinline__ float2 unpack2(u64 v) {
    float x, y; asm("mov.b64 {%0,%1}, %2;" : "=f"(x), "=f"(y) : "l"(v));
    return make_float2(x, y);
}

// ---------------- scratch (device globals; no allocation) ----------------
__device__ float g_xin [T*B*D];
__device__ float g_trig[T*B*D];
__device__ float g_qk  [T*NH*B*D];
__device__ float g_ipre[T*HB];
__device__ float g_fpre[T*HB];
__device__ float g_ad  [T*HB];
__device__ float g_bd  [T*HB];
__device__ float g_q [NH*B*T*D];     // [hb][t][e]
__device__ float g_k [NH*B*T*D];
__device__ float g_v [NH*B*T*D];
__device__ float g_og[NH*B*T*D];
__device__ float g_sk[NH*B*T*D];
__device__ float g_h [T*NH*B*D];     // [t][h][b][d]
__device__ float g_hn[T*B*NH*D];     // BN2'd, [(t*B+b)][h*D+d]
__device__ float g_pp[4*T*B*D];      // poll partials [kz][(t*B+b)][e]

// ---------------- K1b: BN1 (inline) + up-proj GEMM [512,128]x[128,512] -------
__global__ __launch_bounds__(256) void k1b(const float* __restrict__ x,
                                           const float* __restrict__ bn1_s,
                                           const float* __restrict__ bn1_b,
                                           const float* __restrict__ Wup1,
                                           const float* __restrict__ bup1,
                                           const float* __restrict__ Wup2,
                                           const float* __restrict__ bup2)
{
    int tm = blockIdx.x;   // 0..7
    int tn = blockIdx.y;   // 0..7

    __shared__ float As[32*68];  // k-major As[c*68 + r]
    __shared__ float Bs[32*68];

    int tid = threadIdx.x;
    int tx = tid & 15;
    int ty = tid >> 4;

    u64 acc2[2][4];
    #pragma unroll
    for (int i = 0; i < 2; i++)
        #pragma unroll
        for (int j = 0; j < 4; j++) acc2[i][j] = 0ull;

    for (int kt = 0; kt < 4; kt++) {
        #pragma unroll
        for (int i = 0; i < 8; i++) {
            int e = tid + 256*i;
            int r = e >> 5, c = e & 31;
            As[c*68 + r] = x[(tm*64 + r)*H + kt*32 + c];
        }
        #pragma unroll
        for (int i = 0; i < 8; i++) {
            int e = tid + 256*i;
            int kr = e >> 6, cc = e & 63;
            int jrow = kt*32 + kr;
            int col = tn*64 + cc;
            float w = (col < 256) ? Wup1[jrow*D + col] : Wup2[jrow*D + col - 256];
            Bs[kr*68 + cc] = w;
        }
        __syncthreads();

        // BN1 inline
        {
            int tl = tid >> 5;
            int c  = tid & 31;
            float* base = &As[c*68 + tl*8];
            float s = 0.f, s2 = 0.f;
            #pragma unroll
            for (int bb = 0; bb < 8; bb++) { float v = base[bb]; s += v; s2 += v*v; }
            float mu  = s * 0.125f;
            float var = s2 * 0.125f - mu*mu;
            float inv = rsqrtf(var + EPS);
            int j = kt*32 + c;
            float sc = bn1_s[j]*inv, ofs = bn1_b[j];
            #pragma unroll
            for (int bb = 0; bb < 8; bb++) base[bb] = (base[bb] - mu)*sc + ofs;
        }
        __syncthreads();

        #pragma unroll
        for (int kk = 0; kk < 32; kk++) {
            const u64* ap2 = (const u64*)&As[kk*68 + ty*4];
            u64 ap[2] = {ap2[0], ap2[1]};
            float4 b4 = *(const float4*)&Bs[kk*68 + tx*4];
            u64 bb[4] = {bcast2(b4.x), bcast2(b4.y), bcast2(b4.z), bcast2(b4.w)};
            #pragma unroll
            for (int i = 0; i < 2; i++)
                #pragma unroll
                for (int j = 0; j < 4; j++) ffma2(acc2[i][j], ap[i], bb[j]);
        }
        __syncthreads();
    }

    bool istrig = (tn >= 4);
    #pragma unroll
    for (int ip = 0; ip < 2; ip++) {
        #pragma unroll
        for (int half = 0; half < 2; half++) {
            int row = tm*64 + ty*4 + ip*2 + half;
            int col = tn*64 + tx*4;
            float rv[4];
            #pragma unroll
            for (int j = 0; j < 4; j++) {
                float2 p = unpack2(acc2[ip][j]);
                rv[j] = half ? p.y : p.x;
            }
            if (!istrig) {
                float4 o;
                o.x = rv[0] + bup1[col+0];
                o.y = rv[1] + bup1[col+1];
                o.z = rv[2] + bup1[col+2];
                o.w = rv[3] + bup1[col+3];
                *(float4*)&g_xin[(size_t)row*D + col] = o;
            } else {
                int c2 = col - 256;
                float4 o; float tv;
                tv = rv[0] + bup2[c2+0]; o.x = tv / (1.f + expf(-tv));
                tv = rv[1] + bup2[c2+1]; o.y = tv / (1.f + expf(-tv));
                tv = rv[2] + bup2[c2+2]; o.z = tv / (1.f + expf(-tv));
                tv = rv[3] + bup2[c2+3]; o.w = tv / (1.f + expf(-tv));
                *(float4*)&g_trig[(size_t)row*D + c2] = o;
            }
        }
    }
}

// ---------------- K1c: conv/qk + gate pre-acts -------------------------------
__global__ __launch_bounds__(256) void k1c(const float* __restrict__ convk,
                                           const float* __restrict__ convb,
                                           const float* __restrict__ Wi,
                                           const float* __restrict__ bi,
                                           const float* __restrict__ Wf,
                                           const float* __restrict__ bf)
{
    int t = blockIdx.x;
    int tid = threadIdx.x;
    __shared__ float xins[B*D];

    for (int i = tid; i < B*D; i += 256) xins[i] = g_xin[(size_t)t*B*D + i];
    __syncthreads();

    for (int idx = tid; idx < NH*B*D; idx += 256) {
        int hh = idx / (B*D);
        int rem = idx % (B*D);
        int bb = rem / D, dd = rem % D;
        float acc = convb[hh];
        #pragma unroll
        for (int w = 0; w < 4; w++) {
            int dj = dd - 1 + w;
            if (dj >= 0 && dj < D) acc = fmaf(xins[bb*D + dj], convk[w*NH + hh], acc);
        }
        g_qk[((t*NH + hh)*B + bb)*D + dd] = acc / (1.f + expf(-acc));
    }

    {
        int g = tid >> 2;
        int r = tid & 3;
        int which = g >> 5;
        int p = g & 31;
        int hh = p >> 3, bb = p & 7;
        const float* W = which ? (Wf + hh*D) : (Wi + hh*D);
        const float* xb = xins + bb*D;
        float acc = 0.f;
        for (int u = 0; u < 64; u++) {
            int dd = r + 4*u;
            acc = fmaf(xb[dd], W[dd], acc);
        }
        acc += __shfl_xor_sync(0xffffffffu, acc, 1);
        acc += __shfl_xor_sync(0xffffffffu, acc, 2);
        if (r == 0) {
            if (which) g_fpre[t*HB + p] = acc + bf[hh];
            else       g_ipre[t*HB + p] = acc + bi[hh];
        }
    }
}

// ---------------- K2: warp-parallel gate scan --------------------------------
__global__ __launch_bounds__(1024) void k2_scan()
{
    __shared__ float si[T*33];
    __shared__ float sf[T*33];
    int tid = threadIdx.x;

    for (int i = tid; i < T*HB; i += 1024) {
        int t = i >> 5, p = i & 31;
        si[t*33 + p] = g_ipre[i];
        sf[t*33 + p] = g_fpre[i];
    }
    __syncthreads();

    int p = tid >> 5;
    int l = tid & 31;
    int t0 = 2*l, t1 = 2*l + 1;
    float f0 = sf[t0*33 + p], f1 = sf[t1*33 + p];
    float i0 = si[t0*33 + p], i1 = si[t1*33 + p];

    float ps = f0 + f1;
    float s = ps;
    #pragma unroll
    for (int d = 1; d < 32; d <<= 1) {
        float o = __shfl_up_sync(0xffffffffu, s, d);
        if (l >= d) s += o;
    }
    float excl = s - ps;
    float cf0 = excl + f0;
    float cf1 = excl + ps;

    float F = f0 + f1;
    float I = fmaxf(i0 + f1, i1);
    #pragma unroll
    for (int d = 1; d < 32; d <<= 1) {
        float Fo = __shfl_up_sync(0xffffffffu, F, d);
        float Io = __shfl_up_sync(0xffffffffu, I, d);
        if (l >= d) {
            I = fmaxf(Io + F, I);
            F = Fo + F;
        }
    }
    float m1 = fmaxf(F, I);
    float Fe = __shfl_up_sync(0xffffffffu, F, 1);
    float Ie = __shfl_up_sync(0xffffffffu, I, 1);
    if (l == 0) { Fe = 0.f; Ie = -3.0e38f; }
    float m0v = fmaxf(Fe + f0, fmaxf(Ie + f0, i0));

    g_ad[t0*HB + p] = i0 - cf0;
    g_ad[t1*HB + p] = i1 - cf1;
    g_bd[t0*HB + p] = cf0 - m0v;
    g_bd[t1*HB + p] = cf1 - m1;
}

// ---------------- K3: batched projection GEMMs (128x64, lean FFMA2) ----------
__global__ __launch_bounds__(256) void k3_gemm(
    const float* __restrict__ Wq, const float* __restrict__ bq,
    const float* __restrict__ Wk, const float* __restrict__ bk,
    const float* __restrict__ Wv, const float* __restrict__ bv,
    const float* __restrict__ Wo, const float* __restrict__ bo,
    const float* __restrict__ Wsk,const float* __restrict__ bsk)
{
    int inst = blockIdx.y;           // 0..19
    int proj = inst / NH;
    int h    = inst % NH;
    int tm = blockIdx.x & 3;
    int tn = blockIdx.x >> 2;

    const float* W; const float* bias; int src;
    switch (proj) {
        case 0: W = Wq;  bias = bq;  src = 0; break;
        case 1: W = Wk;  bias = bk;  src = 0; break;
        case 2: W = Wv;  bias = bv;  src = 1; break;
        case 3: W = Wo;  bias = bo;  src = 1; break;
        default:W = Wsk; bias = bsk; src = 0; break;
    }

    __shared__ float As[32*132];  // k-major As[c*132 + r], r<128
    __shared__ float Bs[32*68];

    int tid = threadIdx.x;
    int tx = tid & 15;
    int ty = tid >> 4;

    u64 acc2[4][4];
    #pragma unroll
    for (int i = 0; i < 4; i++)
        #pragma unroll
        for (int j = 0; j < 4; j++) acc2[i][j] = 0ull;

    const float* Wb = W + (size_t)h*D*D;

    for (int kt = 0; kt < 8; kt++) {
        // A: 128x32 tile, vectorized LDG.128 + scatter STS
        #pragma unroll
        for (int i = 0; i < 4; i++) {
            int v = tid + 256*i;       // 0..1023
            int r = v >> 3;            // 0..127
            int c4 = v & 7;
            int gr = tm*128 + r;
            int t = gr >> 3, bb = gr & 7;
            const float* srcp = (src == 0)
                ? &g_qk[((t*NH + h)*B + bb)*D + kt*32 + c4*4]
                : &g_xin[(t*B + bb)*D + kt*32 + c4*4];
            float4 av = *(const float4*)srcp;
            As[(c4*4+0)*132 + r] = av.x;
            As[(c4*4+1)*132 + r] = av.y;
            As[(c4*4+2)*132 + r] = av.z;
            As[(c4*4+3)*132 + r] = av.w;
        }
        // B: 32x64 tile, vectorized
        #pragma unroll
        for (int i = 0; i < 2; i++) {
            int v = tid + 256*i;       // 0..511
            int kr = v >> 4;           // 0..31
            int c4 = v & 15;
            *(float4*)&Bs[kr*68 + c4*4] =
                *(const float4*)&Wb[(kt*32 + kr)*D + tn*64 + c4*4];
        }
        __syncthreads();
        #pragma unroll
        for (int kk = 0; kk < 32; kk++) {
            const u64* ap2 = (const u64*)&As[kk*132 + ty*8];
            u64 ap[4] = {ap2[0], ap2[1], ap2[2], ap2[3]};
            float4 b4 = *(const float4*)&Bs[kk*68 + tx*4];
            u64 bb2[4] = {bcast2(b4.x), bcast2(b4.y), bcast2(b4.z), bcast2(b4.w)};
            #pragma unroll
            for (int i = 0; i < 4; i++)
                #pragma unroll
                for (int j = 0; j < 4; j++) ffma2(acc2[i][j], ap[i], bb2[j]);
        }
        __syncthreads();
    }

    #pragma unroll
    for (int ip = 0; ip < 4; ip++) {
        #pragma unroll
        for (int half = 0; half < 2; half++) {
            int gr = tm*128 + ty*8 + ip*2 + half;
            int t = gr >> 3, bb = gr & 7;
            #pragma unroll
            for (int j = 0; j < 4; j++) {
                float2 pr = unpack2(acc2[ip][j]);
                float v = (half ? pr.y : pr.x);
                int e = tn*64 + tx*4 + j;
                v += bias[h*D + e];
                size_t oidx = ((size_t)(h*B + bb)*T + t)*D + e;
                switch (proj) {
                    case 0: g_q [oidx] = v; break;
                    case 1: g_k [oidx] = v * INV_SQRT_D; break;
                    case 2: g_v [oidx] = v; break;
                    case 3: g_og[oidx] = 1.f / (1.f + expf(-v)); break;
                    default:g_sk[oidx] = v; break;
                }
            }
        }
    }
}

// ---------------- K4: fused S=QK^T + decay/mask/rowsum + O=W.V ---------------
// grid (HB, 2): block recomputes full S (in regs), outputs e-slice [y*128..)
__global__ __launch_bounds__(256) void k4()
{
    __shared__ float WsT[64*68];    // phase2: Q-chunk [c<32][r<64]; phase3+: W^T [s][t]
    __shared__ float Ks [32*68];    // phase2: K-chunk
    __shared__ float Vs [64*132];   // phase3+: V [s][el<128]
    __shared__ float ad_s[64];
    __shared__ float bd_s[64];
    __shared__ float sc_s[64];

    int hb = blockIdx.x;
    int h = hb >> 3, b = hb & 7;
    int eoff = blockIdx.y * 128;
    int tid = threadIdx.x;
    int tx = tid & 15;
    int ty = tid >> 4;

    if (tid < 64) {
        ad_s[tid] = g_ad[tid*HB + hb];
        bd_s[tid] = g_bd[tid*HB + hb];
    }

    const float* Qg = g_q + (size_t)hb*T*D;
    const float* Kg = g_k + (size_t)hb*T*D;

    u64 acc2[2][4];
    #pragma unroll
    for (int i = 0; i < 2; i++)
        #pragma unroll
        for (int j = 0; j < 4; j++) acc2[i][j] = 0ull;

    // phase 2: S = Q.K^T over 256 e in 8 chunks of 32 (thread tile 4x4)
    for (int ch = 0; ch < 8; ch++) {
        #pragma unroll
        for (int i = 0; i < 2; i++) {
            int v = tid + 256*i;      // 0..511
            int r = v >> 3;           // 0..63
            int c4 = v & 7;
            float4 qv = *(const float4*)&Qg[r*D + ch*32 + c4*4];
            float4 kv = *(const float4*)&Kg[r*D + ch*32 + c4*4];
            WsT[(c4*4+0)*68 + r] = qv.x;
            WsT[(c4*4+1)*68 + r] = qv.y;
            WsT[(c4*4+2)*68 + r] = qv.z;
            WsT[(c4*4+3)*68 + r] = qv.w;
            Ks [(c4*4+0)*68 + r] = kv.x;
            Ks [(c4*4+1)*68 + r] = kv.y;
            Ks [(c4*4+2)*68 + r] = kv.z;
            Ks [(c4*4+3)*68 + r] = kv.w;
        }
        __syncthreads();
        #pragma unroll
        for (int kk = 0; kk < 32; kk++) {
            const u64* ap2 = (const u64*)&WsT[kk*68 + ty*4];
            u64 ap[2] = {ap2[0], ap2[1]};
            float4 b4 = *(const float4*)&Ks[kk*68 + tx*4];
            u64 bb[4] = {bcast2(b4.x), bcast2(b4.y), bcast2(b4.z), bcast2(b4.w)};
            #pragma unroll
            for (int i = 0; i < 2; i++)
                #pragma unroll
                for (int j = 0; j < 4; j++) ffma2(acc2[i][j], ap[i], bb[j]);
        }
        __syncthreads();
    }

    // phase 3: decay/mask into WsT (transposed), load V slice
    float wreg[4][4];
    #pragma unroll
    for (int ip = 0; ip < 2; ip++) {
        #pragma unroll
        for (int half = 0; half < 2; half++) {
            int t = ty*4 + ip*2 + half;
            float bdv = bd_s[t];
            #pragma unroll
            for (int j = 0; j < 4; j++) {
                int s = tx*4 + j;
                float2 pr = unpack2(acc2[ip][j]);
                float val = half ? pr.y : pr.x;
                wreg[ip*2 + half][j] = (s <= t) ? expf(ad_s[s] + bdv) * val : 0.f;
            }
        }
    }
    __syncthreads();   // done reading Q-chunk region before overwrite
    #pragma unroll
    for (int i = 0; i < 4; i++) {
        int t = ty*4 + i;
        #pragma unroll
        for (int j = 0; j < 4; j++)
            WsT[(tx*4 + j)*68 + t] = wreg[i][j];
    }
    const float* Vg = g_v + (size_t)hb*T*D;
    #pragma unroll
    for (int i = 0; i < 8; i++) {
        int v = tid + 256*i;          // 0..2047
        int s = v >> 5, e4 = v & 31;
        *(float4*)&Vs[s*132 + e4*4] =
            *(const float4*)&Vg[s*D + eoff + e4*4];
    }
    __syncthreads();

    // phase 4: rowsum -> scaler
    if (tid < 64) {
        float r = 0.f;
        #pragma unroll 8
        for (int s = 0; s < 64; s++) r += WsT[s*68 + tid];
        sc_s[tid] = 1.f / fmaxf(fabsf(r), 1.f);
    }
    __syncthreads();

    // phase 5: O = W.V  (thread tile 4t x 8e; B-paired FFMA2)
    u64 oacc[4][4];   // [t_i][e_pair]
    #pragma unroll
    for (int i = 0; i < 4; i++)
        #pragma unroll
        for (int j = 0; j < 4; j++) oacc[i][j] = 0ull;

    #pragma unroll 4
    for (int s = 0; s < 64; s++) {
        float4 w4 = *(const float4*)&WsT[s*68 + ty*4];
        const u64* bp = (const u64*)&Vs[s*132 + tx*8];
        u64 bb[4] = {bp[0], bp[1], bp[2], bp[3]};
        u64 aw[4] = {bcast2(w4.x), bcast2(w4.y), bcast2(w4.z), bcast2(w4.w)};
        #pragma unroll
        for (int i = 0; i < 4; i++)
            #pragma unroll
            for (int j = 0; j < 4; j++) ffma2(oacc[i][j], aw[i], bb[j]);
    }

    const float* OGg = g_og + (size_t)hb*T*D;
    const float* SKg = g_sk + (size_t)hb*T*D;
    #pragma unroll
    for (int i = 0; i < 4; i++) {
        int t = ty*4 + i;
        float scv = sc_s[t];
        float av[8];
        #pragma unroll
        for (int j = 0; j < 4; j++) {
            float2 pr = unpack2(oacc[i][j]);
            av[2*j] = pr.x; av[2*j+1] = pr.y;
        }
        #pragma unroll
        for (int q = 0; q < 2; q++) {
            int ecol = eoff + tx*8 + q*4;
            float4 og4 = *(const float4*)&OGg[t*D + ecol];
            float4 sk4 = *(const float4*)&SKg[t*D + ecol];
            float4 hv;
            hv.x = og4.x * av[q*4+0] * scv + sk4.x;
            hv.y = og4.y * av[q*4+1] * scv + sk4.y;
            hv.z = og4.z * av[q*4+2] * scv + sk4.z;
            hv.w = og4.w * av[q*4+3] * scv + sk4.w;
            *(float4*)&g_h[((size_t)(t*NH + h)*B + b)*D + ecol] = hv;
        }
    }
}

// ---------------- K5a: BN2 + re-layout ---------------------------------------
__global__ __launch_bounds__(256) void k5a(const float* __restrict__ bn2_s,
                                           const float* __restrict__ bn2_b)
{
    int t = blockIdx.x;
    int tid = threadIdx.x;
    __shared__ float hs[32*257];

    for (int i = tid; i < 32*256; i += 256) {
        int p = i >> 8, d = i & 255;
        hs[p*257 + d] = g_h[(size_t)t*NH*B*D + p*256 + d];
    }
    __syncthreads();

    int d = tid;
    float s = 0.f, s2 = 0.f;
    #pragma unroll
    for (int p = 0; p < 32; p++) { float v = hs[p*257 + d]; s += v; s2 += v*v; }
    float mu  = s * (1.f/32);
    float var = s2 * (1.f/32) - mu*mu;
    float inv = rsqrtf(var + EPS);
    float sc = bn2_s[d]*inv, ofs = bn2_b[d];
    #pragma unroll
    for (int p = 0; p < 32; p++) {
        int hh = p >> 3, bb = p & 7;
        g_hn[(size_t)(t*B + bb)*(NH*D) + hh*D + d] = (hs[p*257 + d] - mu)*sc + ofs;
    }
}

// ---------------- K5b: poll GEMM, K-split 4, lean FFMA2 ----------------------
__global__ __launch_bounds__(256) void k5b(const float* __restrict__ Wpoll)
{
    int tm = blockIdx.x;
    int tn = blockIdx.y;
    int kz = blockIdx.z;

    __shared__ float As[32*68];
    __shared__ float Bs[32*68];

    int tid = threadIdx.x;
    int tx = tid & 15;
    int ty = tid >> 4;

    u64 acc2[2][4];
    #pragma unroll
    for (int i = 0; i < 2; i++)
        #pragma unroll
        for (int j = 0; j < 4; j++) acc2[i][j] = 0ull;

    for (int kt = 0; kt < 8; kt++) {
        int k0 = kz*256 + kt*32;
        #pragma unroll
        for (int i = 0; i < 2; i++) {
            int v = tid + 256*i;      // 0..511
            int r = v >> 3;           // 0..63
            int c4 = v & 7;
            float4 av = *(const float4*)&g_hn[(size_t)(tm*64 + r)*(NH*D) + k0 + c4*4];
            As[(c4*4+0)*68 + r] = av.x;
            As[(c4*4+1)*68 + r] = av.y;
            As[(c4*4+2)*68 + r] = av.z;
            As[(c4*4+3)*68 + r] = av.w;
        }
        #pragma unroll
        for (int i = 0; i < 2; i++) {
            int v = tid + 256*i;
            int kr = v >> 4, c4 = v & 15;
            *(float4*)&Bs[kr*68 + c4*4] =
                *(const float4*)&Wpoll[(size_t)(k0 + kr)*D + tn*64 + c4*4];
        }
        __syncthreads();
        #pragma unroll
        for (int kk = 0; kk < 32; kk++) {
            const u64* ap2 = (const u64*)&As[kk*68 + ty*4];
            u64 ap[2] = {ap2[0], ap2[1]};
            float4 b4 = *(const float4*)&Bs[kk*68 + tx*4];
            u64 bb[4] = {bcast2(b4.x), bcast2(b4.y), bcast2(b4.z), bcast2(b4.w)};
            #pragma unroll
            for (int i = 0; i < 2; i++)
                #pragma unroll
                for (int j = 0; j < 4; j++) ffma2(acc2[i][j], ap[i], bb[j]);
        }
        __syncthreads();
    }

    #pragma unroll
    for (int ip = 0; ip < 2; ip++) {
        float2 p0 = unpack2(acc2[ip][0]);
        float2 p1 = unpack2(acc2[ip][1]);
        float2 p2 = unpack2(acc2[ip][2]);
        float2 p3 = unpack2(acc2[ip][3]);
        int row0 = tm*64 + ty*4 + ip*2;
        *(float4*)&g_pp[(size_t)kz*T*B*D + (size_t)row0*D + tn*64 + tx*4] =
            make_float4(p0.x, p1.x, p2.x, p3.x);
        *(float4*)&g_pp[(size_t)kz*T*B*D + (size_t)(row0+1)*D + tn*64 + tx*4] =
            make_float4(p0.y, p1.y, p2.y, p3.y);
    }
}

// ---------------- K5c: combine partials + trig gate + down + residual --------
__global__ __launch_bounds__(256) void k5c(
    const float* __restrict__ x,
    const float* __restrict__ bpoll,
    const float* __restrict__ Wdown, const float* __restrict__ bdown,
    float* __restrict__ out)
{
    int t = blockIdx.x;
    int tid = threadIdx.x;
    __shared__ float ps[B*D];

    for (int i = tid; i < B*D; i += 256) {
        int bb = i >> 8, e = i & 255;
        size_t row = (size_t)(t*B + bb)*D + e;
        float pv = g_pp[row] + g_pp[(size_t)T*B*D + row]
                 + g_pp[(size_t)2*T*B*D + row] + g_pp[(size_t)3*T*B*D + row]
                 + bpoll[e];
        ps[bb*D + e] = pv * g_trig[row];
    }
    __syncthreads();

    int j = tid & 127;
    int bg = tid >> 7;
    float acc[4] = {0.f, 0.f, 0.f, 0.f};
    for (int e = 0; e < D; e++) {
        float w = Wdown[e*H + j];
        #pragma unroll
        for (int q = 0; q < 4; q++) acc[q] = fmaf(ps[(bg*4 + q)*D + e], w, acc[q]);
    }
    #pragma unroll
    for (int q = 0; q < 4; q++) {
        int bb = bg*4 + q;
        out[(t*B + bb)*H + j] = acc[q] + bdown[j] + x[(t*B + bb)*H + j];
    }
}

// ---------------- launch -----------------------------------------------------
extern "C" void kernel_launch(void* const* d_in, const int* in_sizes, int n_in,
                              void* d_out, int out_size)
{
    const float* x      = (const float*)d_in[0];
    const float* Wq     = (const float*)d_in[1];
    const float* bq     = (const float*)d_in[2];
    const float* Wk     = (const float*)d_in[3];
    const float* bk     = (const float*)d_in[4];
    const float* Wv     = (const float*)d_in[5];
    const float* bv     = (const float*)d_in[6];
    const float* convk  = (const float*)d_in[7];
    const float* convb  = (const float*)d_in[8];
    const float* Wi     = (const float*)d_in[9];
    const float* bi     = (const float*)d_in[10];
    const float* Wf     = (const float*)d_in[11];
    const float* bf     = (const float*)d_in[12];
    const float* Wo     = (const float*)d_in[13];
    const float* bo     = (const float*)d_in[14];
    const float* Wsk    = (const float*)d_in[15];
    const float* bsk    = (const float*)d_in[16];
    const float* bn1_s  = (const float*)d_in[17];
    const float* bn1_b  = (const float*)d_in[18];
    const float* bn2_s  = (const float*)d_in[19];
    const float* bn2_b  = (const float*)d_in[20];
    const float* Wup1   = (const float*)d_in[21];
    const float* bup1   = (const float*)d_in[22];
    const float* Wup2   = (const float*)d_in[23];
    const float* bup2   = (const float*)d_in[24];
    const float* Wpoll  = (const float*)d_in[25];
    const float* bpoll  = (const float*)d_in[26];
    const float* Wdown  = (const float*)d_in[27];
    const float* bdown  = (const float*)d_in[28];
    float* out = (float*)d_out;

    k1b<<<dim3(8, 8), 256>>>(x, bn1_s, bn1_b, Wup1, bup1, Wup2, bup2);
    k1c<<<T, 256>>>(convk, convb, Wi, bi, Wf, bf);
    k2_scan<<<1, 1024>>>();
    k3_gemm<<<dim3(16, 20), 256>>>(Wq, bq, Wk, bk, Wv, bv, Wo, bo, Wsk, bsk);
    k4<<<dim3(HB, 2), 256>>>();
    k5a<<<T, 256>>>(bn2_s, bn2_b);
    k5b<<<dim3(8, 4, 4), 256>>>(Wpoll);
    k5c<<<T, 256>>>(x, bpoll, Wdown, bdown, out);
}